// round 8
// baseline (speedup 1.0000x reference)
#include <cuda_runtime.h>
#include <cuda_bf16.h>
#include <cstdint>

// Problem constants (fixed-shape problem)
#define NN      50000
#define EE_MAX  800000
#define GG      128
#define DINF    200
#define DHF     128
#define NLAY    4
#define BN_EPS  1e-5f
#define OUTW    (DINF + NLAY * DHF)   // 712
#define BNP_ROWS 128
#define WPAIRS  548                   // total bf16-pair rows across all 8 weights
#define APK_W   50                    // max packed uint4 per row (K=200 -> 50)

// ---------------- scratch (device globals; no allocation allowed) ----------
__device__ uint4 g_apk    [NN * APK_W];  // packed A: (hi01,hi23,lo01,lo23) per 4 k
__device__ float g_mid    [NN * DHF];
__device__ float g_rep    [NN * DHF];
__device__ float g_h      [NN * DHF];
__device__ int   g_cnt    [2 * NN];      // [0,NN): hist, [NN,2NN): scatter cursor
__device__ int   g_rowptr [NN + 1];
__device__ int   g_colidx [EE_MAX];
__device__ float g_sum    [2 * NLAY][DHF];
__device__ float g_sumsq  [2 * NLAY][DHF];
__device__ uint2 g_wpk    [WPAIRS * DHF];   // .x = hi bf16x2, .y = lo bf16x2

// ---------------- bf16 hi/lo split helpers ---------------------------------
__device__ __forceinline__ uint32_t pack_bf16(float v0, float v1, float& rem0, float& rem1) {
    __nv_bfloat16 h0 = __float2bfloat16(v0);
    __nv_bfloat16 h1 = __float2bfloat16(v1);
    rem0 = v0 - __bfloat162float(h0);
    rem1 = v1 - __bfloat162float(h1);
    return ((uint32_t)__bfloat16_as_ushort(h1) << 16) | (uint32_t)__bfloat16_as_ushort(h0);
}
__device__ __forceinline__ uint32_t pack_bf16_rn(float v0, float v1) {
    __nv_bfloat162 p = __floats2bfloat162_rn(v0, v1);   // .x = v0 (low half)
    return *(uint32_t*)&p;
}

// ---------------- weight prepack + hist-counter zeroing (launch #1) --------
//  [0,100)   w1_0 (K=200)        [100,164) w2_0
//  [164,228) w1_r[0]  [228,292) w1_r[1]  [292,356) w1_r[2]
//  [356,420) w2_r[0]  [420,484) w2_r[1]  [484,548) w2_r[2]
__global__ void k_packw(const float* __restrict__ w1_0, const float* __restrict__ w2_0,
                        const float* __restrict__ w1_r, const float* __restrict__ w2_r) {
    int b = blockIdx.x;        // pair-row 0..547
    int c = threadIdx.x;       // column 0..127
    // zero hist counters (re-run safe: every replay must reset them)
    for (int i = b * DHF + c; i < NN; i += WPAIRS * DHF) g_cnt[i] = 0;

    const float* src;
    int kp;
    if (b < 100)      { src = w1_0; kp = b; }
    else if (b < 164) { src = w2_0; kp = b - 100; }
    else {
        int r = b - 164;
        if (r < 192) { src = w1_r + (r / 64) * DHF * DHF; kp = r % 64; }
        else { r -= 192; src = w2_r + (r / 64) * DHF * DHF; kp = r % 64; }
    }
    float v0 = src[(size_t)(2 * kp) * DHF + c];
    float v1 = src[(size_t)(2 * kp + 1) * DHF + c];
    float r0, r1;
    uint32_t hi = pack_bf16(v0, v1, r0, r1);
    uint32_t lo = pack_bf16_rn(r0, r1);
    g_wpk[b * DHF + c] = make_uint2(hi, lo);
}

// ---------------- CSR build ------------------------------------------------
__global__ void k_hist(const int* __restrict__ erow, int E) {
    int e = blockIdx.x * blockDim.x + threadIdx.x;
    if (e < E) atomicAdd(&g_cnt[erow[e]], 1);
}

// single-block scan; also zeroes scatter cursors, BN stats, and `out`.
__global__ void k_scan_big(float* __restrict__ out, int out_n) {
    extern __shared__ int sc[];            // [NN] + [1024] partials
    int* part = sc + NN;
    const int T = 1024;
    int t = threadIdx.x;

    if (t < DHF) {
        for (int l = 0; l < 2 * NLAY; l++) { g_sum[l][t] = 0.f; g_sumsq[l][t] = 0.f; }
    }
    for (int i = t; i < out_n; i += T) out[i] = 0.f;
    for (int i = t; i < NN; i += T) {
        sc[i] = g_cnt[i];
        g_cnt[NN + i] = 0;
    }
    __syncthreads();

    const int C = (NN + T - 1) / T;
    int base = t * C;
    int s = 0;
    for (int j = 0; j < C; j++) {
        int i = base + j;
        if (i < NN) s += sc[i];
    }
    part[t] = s;
    __syncthreads();
    for (int off = 1; off < T; off <<= 1) {
        int v = (t >= off) ? part[t - off] : 0;
        __syncthreads();
        part[t] += v;
        __syncthreads();
    }
    int pre = (t > 0) ? part[t - 1] : 0;
    for (int j = 0; j < C; j++) {
        int i = base + j;
        if (i < NN) {
            int c = sc[i];
            sc[i] = pre;
            pre += c;
        }
    }
    __syncthreads();
    for (int i = t; i < NN; i += T) g_rowptr[i] = sc[i];
    if (t == T - 1) g_rowptr[NN] = pre;
}

__global__ void k_scatter(const int* __restrict__ erow, const int* __restrict__ ecol, int E) {
    int e = blockIdx.x * blockDim.x + threadIdx.x;
    if (e < E) {
        int r = erow[e];
        int p = g_rowptr[r] + atomicAdd(&g_cnt[NN + r], 1);
        g_colidx[p] = ecol[e];
    }
}

// ---------------- SpMM (pull / CSR) with packed-bf16 output ----------------
// pooled[i] = sum_edges h[col] + (1+eps)*h[i], emitted as hi/lo bf16 uint4.
template <int D4>
__global__ void k_spmm(const float* __restrict__ hin, uint4* __restrict__ pout,
                       const float* __restrict__ epsv, int li) {
    int wid  = blockIdx.x * 8 + (threadIdx.x >> 5);
    int lane = threadIdx.x & 31;
    if (wid >= NN) return;
    const int S = (D4 + 31) / 32;
    float se = 1.0f + epsv[li];

    const float4* selfr = (const float4*)hin + (size_t)wid * D4;
    float4 acc[S];
#pragma unroll
    for (int s = 0; s < S; s++) {
        int j = lane + 32 * s;
        if (j < D4) {
            float4 v = selfr[j];
            acc[s] = make_float4(v.x * se, v.y * se, v.z * se, v.w * se);
        } else acc[s] = make_float4(0.f, 0.f, 0.f, 0.f);
    }
    int e0 = g_rowptr[wid], e1 = g_rowptr[wid + 1];
    int e = e0;
    for (; e + 2 <= e1; e += 2) {
        int c0 = g_colidx[e], c1 = g_colidx[e + 1];
        const float4* r0 = (const float4*)hin + (size_t)c0 * D4;
        const float4* r1 = (const float4*)hin + (size_t)c1 * D4;
#pragma unroll
        for (int s = 0; s < S; s++) {
            int j = lane + 32 * s;
            if (j < D4) {
                float4 v0 = r0[j], v1 = r1[j];
                acc[s].x += v0.x + v1.x; acc[s].y += v0.y + v1.y;
                acc[s].z += v0.z + v1.z; acc[s].w += v0.w + v1.w;
            }
        }
    }
    if (e < e1) {
        int c = g_colidx[e];
        const float4* r = (const float4*)hin + (size_t)c * D4;
#pragma unroll
        for (int s = 0; s < S; s++) {
            int j = lane + 32 * s;
            if (j < D4) {
                float4 v = r[j];
                acc[s].x += v.x; acc[s].y += v.y; acc[s].z += v.z; acc[s].w += v.w;
            }
        }
    }
    uint4* o = pout + (size_t)wid * D4;
#pragma unroll
    for (int s = 0; s < S; s++) {
        int j = lane + 32 * s;
        if (j < D4) {
            float r0, r1, r2, r3;
            uint32_t h01 = pack_bf16(acc[s].x, acc[s].y, r0, r1);
            uint32_t h23 = pack_bf16(acc[s].z, acc[s].w, r2, r3);
            o[j] = make_uint4(h01, h23, pack_bf16_rn(r0, r1), pack_bf16_rn(r2, r3));
        }
    }
}

// ---------------- 3xBF16 tensor-core GEMM (double-buffered) ----------------
// PACKED=1: A comes pre-split as uint4 per 4-k group (no BN).
// PACKED=0: A fp32 with in-kernel BN+ReLU from (psum,psq,bnga,bnbe).
__device__ __forceinline__ void mma16(float* c, const uint32_t* a, const uint32_t* b) {
    asm volatile(
        "mma.sync.aligned.m16n8k16.row.col.f32.bf16.bf16.f32 "
        "{%0,%1,%2,%3}, {%4,%5,%6,%7}, {%8,%9}, {%0,%1,%2,%3};"
        : "+f"(c[0]), "+f"(c[1]), "+f"(c[2]), "+f"(c[3])
        : "r"(a[0]), "r"(a[1]), "r"(a[2]), "r"(a[3]), "r"(b[0]), "r"(b[1]));
}

template <int PACKED>
__global__ __launch_bounds__(512, 2)
void k_gemm_tc(const float* __restrict__ A, const uint4* __restrict__ Apk,
               const uint2* __restrict__ wpk,
               const float* __restrict__ bias, float* __restrict__ C,
               int M, int K,
               const float* __restrict__ bnga, const float* __restrict__ bnbe,
               const float* __restrict__ psum, const float* __restrict__ psq,
               float* __restrict__ osum, float* __restrict__ osumsq) {
    __shared__ uint32_t ash[2][8][136], asl[2][8][136];
    __shared__ uint32_t wsh[2][8][136], wsl[2][8][136];
    __shared__ float strs[DHF], strh[DHF];

    const int tid  = threadIdx.x;
    const int lane = tid & 31;
    const int wid  = tid >> 5;
    const int wr   = wid >> 2;
    const int wc   = wid & 3;
    const int gid  = lane >> 2;
    const int tq   = lane & 3;
    const int row0 = blockIdx.x * 128;

    const int ar = tid & 127;    // A row within tile / W column
    const int kg = tid >> 7;     // 0..3

    const int KP  = K >> 1;      // weight pair-rows
    const int KP4 = K >> 2;      // packed-A groups per row

    if (!PACKED) {
        if (bnga && tid < DHF) {
            const float invN = 1.0f / NN;
            float m = psum[tid] * invN;
            float v = psq[tid] * invN - m * m;
            float rs = rsqrtf(v + BN_EPS);
            float sc = bnga[tid] * rs;
            strs[tid] = sc;
            strh[tid] = bnbe[tid] - m * sc;
        }
        __syncthreads();
    }

    float acc[2][4][4];
#pragma unroll
    for (int mt = 0; mt < 2; mt++)
#pragma unroll
        for (int nt = 0; nt < 4; nt++)
#pragma unroll
            for (int j = 0; j < 4; j++) acc[mt][nt][j] = 0.f;

    const int T = (K + 15) >> 4;
    const int gr = row0 + ar;
    const bool rok = (gr < M);

    float4 va;
    uint4 pa;
    uint2 wk0, wk1;

    auto prefetch = [&](int t) {
        if (PACKED) {
            int gp = t * 4 + kg;
            pa = make_uint4(0u, 0u, 0u, 0u);
            if (rok && gp < KP4) pa = Apk[(size_t)gr * KP4 + gp];
        } else {
            int gk0 = t * 16 + 4 * kg;
            va = make_float4(0.f, 0.f, 0.f, 0.f);
            if (rok && gk0 < K) va = *(const float4*)&A[(size_t)gr * K + gk0];
        }
        int kp0 = t * 8 + 2 * kg;
        wk0 = (kp0 < KP)     ? wpk[kp0 * DHF + ar]       : make_uint2(0u, 0u);
        wk1 = (kp0 + 1 < KP) ? wpk[(kp0 + 1) * DHF + ar] : make_uint2(0u, 0u);
    };

    auto stage = [&](int d, int k0) {
        if (PACKED) {
            ash[d][2 * kg][ar]     = pa.x;
            ash[d][2 * kg + 1][ar] = pa.y;
            asl[d][2 * kg][ar]     = pa.z;
            asl[d][2 * kg + 1][ar] = pa.w;
        } else {
            float a4[4] = {va.x, va.y, va.z, va.w};
            if (bnga && rok) {
#pragma unroll
                for (int j = 0; j < 4; j++) {
                    int gk = k0 + 4 * kg + j;
                    a4[j] = (gk < K) ? fmaxf(a4[j] * strs[gk] + strh[gk], 0.f) : 0.f;
                }
            }
#pragma unroll
            for (int p = 0; p < 2; p++) {
                float r0f, r1f;
                ash[d][2 * kg + p][ar] = pack_bf16(a4[2 * p], a4[2 * p + 1], r0f, r1f);
                asl[d][2 * kg + p][ar] = pack_bf16_rn(r0f, r1f);
            }
        }
        wsh[d][2 * kg][ar]     = wk0.x;
        wsl[d][2 * kg][ar]     = wk0.y;
        wsh[d][2 * kg + 1][ar] = wk1.x;
        wsl[d][2 * kg + 1][ar] = wk1.y;
    };

    prefetch(0);
    stage(0, 0);
    __syncthreads();

    for (int t = 0; t < T; t++) {
        const int cur = t & 1;
        if (t + 1 < T) prefetch(t + 1);

        {
            uint32_t bh[4][2], bl[4][2];
#pragma unroll
            for (int nt = 0; nt < 4; nt++) {
                int col = wc * 32 + nt * 8 + gid;
                bh[nt][0] = wsh[cur][tq][col];
                bh[nt][1] = wsh[cur][tq + 4][col];
                bl[nt][0] = wsl[cur][tq][col];
                bl[nt][1] = wsl[cur][tq + 4][col];
            }
#pragma unroll
            for (int mt = 0; mt < 2; mt++) {
                int r0 = wr * 32 + mt * 16;
                uint32_t ah[4], al[4];
                ah[0] = ash[cur][tq][r0 + gid];
                ah[1] = ash[cur][tq][r0 + gid + 8];
                ah[2] = ash[cur][tq + 4][r0 + gid];
                ah[3] = ash[cur][tq + 4][r0 + gid + 8];
                al[0] = asl[cur][tq][r0 + gid];
                al[1] = asl[cur][tq][r0 + gid + 8];
                al[2] = asl[cur][tq + 4][r0 + gid];
                al[3] = asl[cur][tq + 4][r0 + gid + 8];
#pragma unroll
                for (int nt = 0; nt < 4; nt++) {
                    mma16(acc[mt][nt], ah, bh[nt]);   // hi*hi
                    mma16(acc[mt][nt], al, bh[nt]);   // lo*hi
                    mma16(acc[mt][nt], ah, bl[nt]);   // hi*lo
                }
            }
        }

        if (t + 1 < T) stage((t + 1) & 1, (t + 1) * 16);
        __syncthreads();
    }

    // ---- epilogue: bias, store, column stats ----
    float cs[4][2], cq[4][2];
#pragma unroll
    for (int nt = 0; nt < 4; nt++)
#pragma unroll
        for (int j = 0; j < 2; j++) { cs[nt][j] = 0.f; cq[nt][j] = 0.f; }

#pragma unroll
    for (int mt = 0; mt < 2; mt++) {
        int rbase = row0 + wr * 32 + mt * 16;
#pragma unroll
        for (int nt = 0; nt < 4; nt++) {
            int colb = wc * 32 + nt * 8 + 2 * tq;
            float b0 = bias[colb], b1 = bias[colb + 1];
            int r1 = rbase + gid;
            int r2 = rbase + gid + 8;
            if (r1 < M) {
                float v0 = acc[mt][nt][0] + b0;
                float v1 = acc[mt][nt][1] + b1;
                *(float2*)&C[(size_t)r1 * 128 + colb] = make_float2(v0, v1);
                cs[nt][0] += v0; cq[nt][0] += v0 * v0;
                cs[nt][1] += v1; cq[nt][1] += v1 * v1;
            }
            if (r2 < M) {
                float v0 = acc[mt][nt][2] + b0;
                float v1 = acc[mt][nt][3] + b1;
                *(float2*)&C[(size_t)r2 * 128 + colb] = make_float2(v0, v1);
                cs[nt][0] += v0; cq[nt][0] += v0 * v0;
                cs[nt][1] += v1; cq[nt][1] += v1 * v1;
            }
        }
    }
#pragma unroll
    for (int nt = 0; nt < 4; nt++)
#pragma unroll
        for (int j = 0; j < 2; j++) {
            float s = cs[nt][j], q = cq[nt][j];
            s += __shfl_xor_sync(0xffffffffu, s, 4);
            s += __shfl_xor_sync(0xffffffffu, s, 8);
            s += __shfl_xor_sync(0xffffffffu, s, 16);
            q += __shfl_xor_sync(0xffffffffu, q, 4);
            q += __shfl_xor_sync(0xffffffffu, q, 8);
            q += __shfl_xor_sync(0xffffffffu, q, 16);
            if (gid == 0) {
                int col = wc * 32 + nt * 8 + 2 * tq + j;
                atomicAdd(&osum[col], s);
                atomicAdd(&osumsq[col], q);
            }
        }
}

// ------ fused BN + ReLU + graph pool, chunk-parallel -----------------------
__global__ void k_bnpool(const float* __restrict__ rep, float* __restrict__ h,
                         float* __restrict__ out, int off,
                         const float* __restrict__ gamma, const float* __restrict__ beta,
                         const int* __restrict__ gids, int slot, int write_h) {
    int c = threadIdx.x;
    int r0 = blockIdx.x * BNP_ROWS;
    int r1 = min(r0 + BNP_ROWS, NN);
    const float invN = 1.0f / NN;
    float m = g_sum[slot][c] * invN;
    float v = g_sumsq[slot][c] * invN - m * m;
    float sc = gamma[c] * rsqrtf(v + BN_EPS);
    float sh = beta[c] - m * sc;

    int curg = gids[r0];
    float acc = 0.f;
    for (int r = r0; r < r1; r++) {
        int gr = gids[r];
        if (gr != curg) {
            atomicAdd(&out[(size_t)curg * OUTW + off + c], acc);
            acc = 0.f;
            curg = gr;
        }
        float xv = fmaxf(rep[(size_t)r * DHF + c] * sc + sh, 0.f);
        if (write_h) h[(size_t)r * DHF + c] = xv;
        acc += xv;
    }
    atomicAdd(&out[(size_t)curg * OUTW + off + c], acc);
}

__global__ void k_poolx(const float* __restrict__ src, float* __restrict__ out,
                        const int* __restrict__ gids) {
    int c = threadIdx.x;
    if (c >= DINF) return;
    int r0 = blockIdx.x * BNP_ROWS;
    int r1 = min(r0 + BNP_ROWS, NN);
    int curg = gids[r0];
    float acc = 0.f;
    for (int r = r0; r < r1; r++) {
        int gr = gids[r];
        if (gr != curg) {
            atomicAdd(&out[(size_t)curg * OUTW + c], acc);
            acc = 0.f;
            curg = gr;
        }
        acc += src[(size_t)r * DINF + c];
    }
    atomicAdd(&out[(size_t)curg * OUTW + c], acc);
}

// ---------------- launch ---------------------------------------------------
extern "C" void kernel_launch(void* const* d_in, const int* in_sizes, int n_in,
                              void* d_out, int out_size) {
    const float* x     = (const float*)d_in[0];
    const int*   erow  = (const int*)d_in[1];
    const int*   ecol  = (const int*)d_in[2];
    const int*   gid   = (const int*)d_in[3];
    const float* eps   = (const float*)d_in[4];
    const float* w1_0  = (const float*)d_in[5];
    const float* b1_0  = (const float*)d_in[6];
    const float* g1_0  = (const float*)d_in[7];
    const float* be1_0 = (const float*)d_in[8];
    const float* w2_0  = (const float*)d_in[9];
    const float* b2_0  = (const float*)d_in[10];
    const float* gbn_0 = (const float*)d_in[11];
    const float* bbn_0 = (const float*)d_in[12];
    const float* w1_r  = (const float*)d_in[13];
    const float* b1_r  = (const float*)d_in[14];
    const float* g1_r  = (const float*)d_in[15];
    const float* be1_r = (const float*)d_in[16];
    const float* w2_r  = (const float*)d_in[17];
    const float* b2_r  = (const float*)d_in[18];
    const float* gbn_r = (const float*)d_in[19];
    const float* bbn_r = (const float*)d_in[20];
    float* out = (float*)d_out;

    int E = in_sizes[1];

    float *mid, *rep, *h, *sumb, *sumsqb;
    uint4 *apk;
    uint2 *wpk;
    cudaGetSymbolAddress((void**)&apk,    g_apk);
    cudaGetSymbolAddress((void**)&mid,    g_mid);
    cudaGetSymbolAddress((void**)&rep,    g_rep);
    cudaGetSymbolAddress((void**)&h,      g_h);
    cudaGetSymbolAddress((void**)&sumb,   g_sum);
    cudaGetSymbolAddress((void**)&sumsqb, g_sumsq);
    cudaGetSymbolAddress((void**)&wpk,    g_wpk);

    const int scan_smem = (NN + 1024) * (int)sizeof(int);
    cudaFuncSetAttribute(k_scan_big, cudaFuncAttributeMaxDynamicSharedMemorySize, scan_smem);

    // launches: packw(1) hist(2) scan(3) scatter(4) spmm(5) gemm1(6) <- ncu -s 5
    k_packw<<<WPAIRS, DHF>>>(w1_0, w2_0, w1_r, w2_r);     // + zero hist counters
    k_hist<<<(E + 255) / 256, 256>>>(erow, E);
    k_scan_big<<<1, 1024, scan_smem>>>(out, out_size);    // + zero cursors/stats/out
    k_scatter<<<(E + 255) / 256, 256>>>(erow, ecol, E);

    const int spmm_blocks = (NN + 7) / 8;
    const int gemm_blocks = (NN + 127) / 128;
    const int pool_blocks = (NN + BNP_ROWS - 1) / BNP_ROWS;

    // pair-row offsets into g_wpk per GEMM segment
    const int woff_g1[NLAY] = {0, 164, 228, 292};
    const int woff_g2[NLAY] = {100, 356, 420, 484};

    for (int l = 0; l < NLAY; l++) {
        const float *ba, *ga, *bea, *bb, *gb, *bbb;
        int K1;
        if (l == 0) {
            k_spmm<DINF / 4><<<spmm_blocks, 256>>>(x, apk, eps, 0);
            K1 = DINF;
            ba = b1_0; ga = g1_0; bea = be1_0;
            bb = b2_0; gb = gbn_0; bbb = bbn_0;
        } else {
            k_spmm<DHF / 4><<<spmm_blocks, 256>>>(h, apk, eps, l);
            K1 = DHF;
            int o1 = (l - 1) * DHF;
            ba = b1_r + o1; ga = g1_r + o1; bea = be1_r + o1;
            bb = b2_r + o1; gb = gbn_r + o1; bbb = bbn_r + o1;
        }

        // GEMM1: packed A from spmm
        k_gemm_tc<1><<<gemm_blocks, 512>>>(nullptr, apk, wpk + woff_g1[l] * DHF,
                                           ba, mid, NN, K1,
                                           nullptr, nullptr, nullptr, nullptr,
                                           sumb + (2 * l) * DHF, sumsqb + (2 * l) * DHF);
        // GEMM2: fp32 A (mid) + in-kernel BN+ReLU from slot-2l stats
        k_gemm_tc<0><<<gemm_blocks, 512>>>(mid, nullptr, wpk + woff_g2[l] * DHF,
                                           bb, rep, NN, DHF,
                                           ga, bea, sumb + (2 * l) * DHF, sumsqb + (2 * l) * DHF,
                                           sumb + (2 * l + 1) * DHF, sumsqb + (2 * l + 1) * DHF);

        k_bnpool<<<pool_blocks, DHF>>>(rep, h, out, DINF + l * DHF, gb, bbb,
                                       gid, 2 * l + 1, (l < NLAY - 1) ? 1 : 0);
    }

    k_poolx<<<pool_blocks, 256>>>(x, out, gid);
}

// round 9
// speedup vs baseline: 1.0971x; 1.0971x over previous
#include <cuda_runtime.h>
#include <cuda_bf16.h>
#include <cstdint>

// Problem constants (fixed-shape problem)
#define NN      50000
#define EE_MAX  800000
#define GG      128
#define DINF    200
#define DHF     128
#define NLAY    4
#define BN_EPS  1e-5f
#define OUTW    (DINF + NLAY * DHF)   // 712
#define BNP_ROWS 32
#define WPAIRS  548
#define APK_W   50

// ---------------- scratch (device globals; no allocation allowed) ----------
__device__ uint4 g_apk    [NN * APK_W];
__device__ float g_mid    [NN * DHF];
__device__ float g_rep    [NN * DHF];
__device__ float g_h      [NN * DHF];
__device__ int   g_cnt    [2 * NN];
__device__ int   g_rowptr [NN + 1];
__device__ int   g_colidx [EE_MAX];
__device__ float g_sum    [2 * NLAY][DHF];
__device__ float g_sumsq  [2 * NLAY][DHF];
__device__ uint2 g_wpk    [WPAIRS * DHF];

// ---------------- bf16 hi/lo split helpers ---------------------------------
__device__ __forceinline__ uint32_t pack_bf16(float v0, float v1, float& rem0, float& rem1) {
    __nv_bfloat16 h0 = __float2bfloat16(v0);
    __nv_bfloat16 h1 = __float2bfloat16(v1);
    rem0 = v0 - __bfloat162float(h0);
    rem1 = v1 - __bfloat162float(h1);
    return ((uint32_t)__bfloat16_as_ushort(h1) << 16) | (uint32_t)__bfloat16_as_ushort(h0);
}
__device__ __forceinline__ uint32_t pack_bf16_rn(float v0, float v1) {
    __nv_bfloat162 p = __floats2bfloat162_rn(v0, v1);
    return *(uint32_t*)&p;
}

// ---------------- weight prepack + hist-counter zeroing --------------------
__global__ void k_packw(const float* __restrict__ w1_0, const float* __restrict__ w2_0,
                        const float* __restrict__ w1_r, const float* __restrict__ w2_r) {
    int b = blockIdx.x;
    int c = threadIdx.x;
    for (int i = b * DHF + c; i < NN; i += WPAIRS * DHF) g_cnt[i] = 0;

    const float* src;
    int kp;
    if (b < 100)      { src = w1_0; kp = b; }
    else if (b < 164) { src = w2_0; kp = b - 100; }
    else {
        int r = b - 164;
        if (r < 192) { src = w1_r + (r / 64) * DHF * DHF; kp = r % 64; }
        else { r -= 192; src = w2_r + (r / 64) * DHF * DHF; kp = r % 64; }
    }
    float v0 = src[(size_t)(2 * kp) * DHF + c];
    float v1 = src[(size_t)(2 * kp + 1) * DHF + c];
    float r0, r1;
    uint32_t hi = pack_bf16(v0, v1, r0, r1);
    uint32_t lo = pack_bf16_rn(r0, r1);
    g_wpk[b * DHF + c] = make_uint2(hi, lo);
}

// ---------------- CSR build ------------------------------------------------
__global__ void k_hist(const int* __restrict__ erow, int E) {
    int e = blockIdx.x * blockDim.x + threadIdx.x;
    if (e < E) atomicAdd(&g_cnt[erow[e]], 1);
}

__global__ void k_scan_big(float* __restrict__ out, int out_n) {
    extern __shared__ int sc[];
    int* part = sc + NN;
    const int T = 1024;
    int t = threadIdx.x;

    if (t < DHF) {
        for (int l = 0; l < 2 * NLAY; l++) { g_sum[l][t] = 0.f; g_sumsq[l][t] = 0.f; }
    }
    for (int i = t; i < out_n; i += T) out[i] = 0.f;
    for (int i = t; i < NN; i += T) {
        sc[i] = g_cnt[i];
        g_cnt[NN + i] = 0;
    }
    __syncthreads();

    const int C = (NN + T - 1) / T;
    int base = t * C;
    int s = 0;
    for (int j = 0; j < C; j++) {
        int i = base + j;
        if (i < NN) s += sc[i];
    }
    part[t] = s;
    __syncthreads();
    for (int off = 1; off < T; off <<= 1) {
        int v = (t >= off) ? part[t - off] : 0;
        __syncthreads();
        part[t] += v;
        __syncthreads();
    }
    int pre = (t > 0) ? part[t - 1] : 0;
    for (int j = 0; j < C; j++) {
        int i = base + j;
        if (i < NN) {
            int c = sc[i];
            sc[i] = pre;
            pre += c;
        }
    }
    __syncthreads();
    for (int i = t; i < NN; i += T) g_rowptr[i] = sc[i];
    if (t == T - 1) g_rowptr[NN] = pre;
}

__global__ void k_scatter(const int* __restrict__ erow, const int* __restrict__ ecol, int E) {
    int e = blockIdx.x * blockDim.x + threadIdx.x;
    if (e < E) {
        int r = erow[e];
        int p = g_rowptr[r] + atomicAdd(&g_cnt[NN + r], 1);
        g_colidx[p] = ecol[e];
    }
}

// ---------------- SpMM (pull / CSR) with packed-bf16 output ----------------
template <int D4>
__global__ void k_spmm(const float* __restrict__ hin, uint4* __restrict__ pout,
                       const float* __restrict__ epsv, int li) {
    int wid  = blockIdx.x * 8 + (threadIdx.x >> 5);
    int lane = threadIdx.x & 31;
    if (wid >= NN) return;
    const int S = (D4 + 31) / 32;
    float se = 1.0f + epsv[li];

    const float4* selfr = (const float4*)hin + (size_t)wid * D4;
    float4 acc[S];
#pragma unroll
    for (int s = 0; s < S; s++) {
        int j = lane + 32 * s;
        if (j < D4) {
            float4 v = selfr[j];
            acc[s] = make_float4(v.x * se, v.y * se, v.z * se, v.w * se);
        } else acc[s] = make_float4(0.f, 0.f, 0.f, 0.f);
    }
    int e0 = g_rowptr[wid], e1 = g_rowptr[wid + 1];
    int e = e0;
    for (; e + 2 <= e1; e += 2) {
        int c0 = g_colidx[e], c1 = g_colidx[e + 1];
        const float4* r0 = (const float4*)hin + (size_t)c0 * D4;
        const float4* r1 = (const float4*)hin + (size_t)c1 * D4;
#pragma unroll
        for (int s = 0; s < S; s++) {
            int j = lane + 32 * s;
            if (j < D4) {
                float4 v0 = r0[j], v1 = r1[j];
                acc[s].x += v0.x + v1.x; acc[s].y += v0.y + v1.y;
                acc[s].z += v0.z + v1.z; acc[s].w += v0.w + v1.w;
            }
        }
    }
    if (e < e1) {
        int c = g_colidx[e];
        const float4* r = (const float4*)hin + (size_t)c * D4;
#pragma unroll
        for (int s = 0; s < S; s++) {
            int j = lane + 32 * s;
            if (j < D4) {
                float4 v = r[j];
                acc[s].x += v.x; acc[s].y += v.y; acc[s].z += v.z; acc[s].w += v.w;
            }
        }
    }
    uint4* o = pout + (size_t)wid * D4;
#pragma unroll
    for (int s = 0; s < S; s++) {
        int j = lane + 32 * s;
        if (j < D4) {
            float r0, r1, r2, r3;
            uint32_t h01 = pack_bf16(acc[s].x, acc[s].y, r0, r1);
            uint32_t h23 = pack_bf16(acc[s].z, acc[s].w, r2, r3);
            o[j] = make_uint4(h01, h23, pack_bf16_rn(r0, r1), pack_bf16_rn(r2, r3));
        }
    }
}

// ---------------- 3xBF16 tensor-core GEMM (double-buffered) ----------------
__device__ __forceinline__ void mma16(float* c, const uint32_t* a, const uint32_t* b) {
    asm volatile(
        "mma.sync.aligned.m16n8k16.row.col.f32.bf16.bf16.f32 "
        "{%0,%1,%2,%3}, {%4,%5,%6,%7}, {%8,%9}, {%0,%1,%2,%3};"
        : "+f"(c[0]), "+f"(c[1]), "+f"(c[2]), "+f"(c[3])
        : "r"(a[0]), "r"(a[1]), "r"(a[2]), "r"(a[3]), "r"(b[0]), "r"(b[1]));
}

template <int PACKED>
__global__ __launch_bounds__(512, 2)
void k_gemm_tc(const float* __restrict__ A, const uint4* __restrict__ Apk,
               const uint2* __restrict__ wpk,
               const float* __restrict__ bias, float* __restrict__ C,
               int M, int K,
               const float* __restrict__ bnga, const float* __restrict__ bnbe,
               const float* __restrict__ psum, const float* __restrict__ psq,
               float* __restrict__ osum, float* __restrict__ osumsq) {
    __shared__ uint32_t ash[2][8][136], asl[2][8][136];
    __shared__ uint32_t wsh[2][8][136], wsl[2][8][136];
    __shared__ float strs[DHF], strh[DHF];

    const int tid  = threadIdx.x;
    const int lane = tid & 31;
    const int wid  = tid >> 5;
    const int wr   = wid >> 2;
    const int wc   = wid & 3;
    const int gid  = lane >> 2;
    const int tq   = lane & 3;
    const int row0 = blockIdx.x * 128;

    const int ar = tid & 127;
    const int kg = tid >> 7;

    const int KP  = K >> 1;
    const int KP4 = K >> 2;

    if (!PACKED) {
        if (bnga && tid < DHF) {
            const float invN = 1.0f / NN;
            float m = psum[tid] * invN;
            float v = psq[tid] * invN - m * m;
            float rs = rsqrtf(v + BN_EPS);
            float sc = bnga[tid] * rs;
            strs[tid] = sc;
            strh[tid] = bnbe[tid] - m * sc;
        }
        __syncthreads();
    }

    float acc[2][4][4];
#pragma unroll
    for (int mt = 0; mt < 2; mt++)
#pragma unroll
        for (int nt = 0; nt < 4; nt++)
#pragma unroll
            for (int j = 0; j < 4; j++) acc[mt][nt][j] = 0.f;

    const int T = (K + 15) >> 4;
    const int gr = row0 + ar;
    const bool rok = (gr < M);

    float4 va;
    uint4 pa;
    uint2 wk0, wk1;

    auto prefetch = [&](int t) {
        if (PACKED) {
            int gp = t * 4 + kg;
            pa = make_uint4(0u, 0u, 0u, 0u);
            if (rok && gp < KP4) pa = Apk[(size_t)gr * KP4 + gp];
        } else {
            int gk0 = t * 16 + 4 * kg;
            va = make_float4(0.f, 0.f, 0.f, 0.f);
            if (rok && gk0 < K) va = *(const float4*)&A[(size_t)gr * K + gk0];
        }
        int kp0 = t * 8 + 2 * kg;
        wk0 = (kp0 < KP)     ? wpk[kp0 * DHF + ar]       : make_uint2(0u, 0u);
        wk1 = (kp0 + 1 < KP) ? wpk[(kp0 + 1) * DHF + ar] : make_uint2(0u, 0u);
    };

    auto stage = [&](int d, int k0) {
        if (PACKED) {
            ash[d][2 * kg][ar]     = pa.x;
            ash[d][2 * kg + 1][ar] = pa.y;
            asl[d][2 * kg][ar]     = pa.z;
            asl[d][2 * kg + 1][ar] = pa.w;
        } else {
            float a4[4] = {va.x, va.y, va.z, va.w};
            if (bnga && rok) {
#pragma unroll
                for (int j = 0; j < 4; j++) {
                    int gk = k0 + 4 * kg + j;
                    a4[j] = (gk < K) ? fmaxf(a4[j] * strs[gk] + strh[gk], 0.f) : 0.f;
                }
            }
#pragma unroll
            for (int p = 0; p < 2; p++) {
                float r0f, r1f;
                ash[d][2 * kg + p][ar] = pack_bf16(a4[2 * p], a4[2 * p + 1], r0f, r1f);
                asl[d][2 * kg + p][ar] = pack_bf16_rn(r0f, r1f);
            }
        }
        wsh[d][2 * kg][ar]     = wk0.x;
        wsl[d][2 * kg][ar]     = wk0.y;
        wsh[d][2 * kg + 1][ar] = wk1.x;
        wsl[d][2 * kg + 1][ar] = wk1.y;
    };

    prefetch(0);
    stage(0, 0);
    __syncthreads();

    for (int t = 0; t < T; t++) {
        const int cur = t & 1;
        if (t + 1 < T) prefetch(t + 1);

        {
            uint32_t bh[4][2], bl[4][2];
#pragma unroll
            for (int nt = 0; nt < 4; nt++) {
                int col = wc * 32 + nt * 8 + gid;
                bh[nt][0] = wsh[cur][tq][col];
                bh[nt][1] = wsh[cur][tq + 4][col];
                bl[nt][0] = wsl[cur][tq][col];
                bl[nt][1] = wsl[cur][tq + 4][col];
            }
#pragma unroll
            for (int mt = 0; mt < 2; mt++) {
                int r0 = wr * 32 + mt * 16;
                uint32_t ah[4], al[4];
                ah[0] = ash[cur][tq][r0 + gid];
                ah[1] = ash[cur][tq][r0 + gid + 8];
                ah[2] = ash[cur][tq + 4][r0 + gid];
                ah[3] = ash[cur][tq + 4][r0 + gid + 8];
                al[0] = asl[cur][tq][r0 + gid];
                al[1] = asl[cur][tq][r0 + gid + 8];
                al[2] = asl[cur][tq + 4][r0 + gid];
                al[3] = asl[cur][tq + 4][r0 + gid + 8];
#pragma unroll
                for (int nt = 0; nt < 4; nt++) {
                    mma16(acc[mt][nt], ah, bh[nt]);
                    mma16(acc[mt][nt], al, bh[nt]);
                    mma16(acc[mt][nt], ah, bl[nt]);
                }
            }
        }

        if (t + 1 < T) stage((t + 1) & 1, (t + 1) * 16);
        __syncthreads();
    }

    // ---- epilogue: bias, store, column stats ----
    float cs[4][2], cq[4][2];
#pragma unroll
    for (int nt = 0; nt < 4; nt++)
#pragma unroll
        for (int j = 0; j < 2; j++) { cs[nt][j] = 0.f; cq[nt][j] = 0.f; }

#pragma unroll
    for (int mt = 0; mt < 2; mt++) {
        int rbase = row0 + wr * 32 + mt * 16;
#pragma unroll
        for (int nt = 0; nt < 4; nt++) {
            int colb = wc * 32 + nt * 8 + 2 * tq;
            float b0 = bias[colb], b1 = bias[colb + 1];
            int r1 = rbase + gid;
            int r2 = rbase + gid + 8;
            if (r1 < M) {
                float v0 = acc[mt][nt][0] + b0;
                float v1 = acc[mt][nt][1] + b1;
                *(float2*)&C[(size_t)r1 * 128 + colb] = make_float2(v0, v1);
                cs[nt][0] += v0; cq[nt][0] += v0 * v0;
                cs[nt][1] += v1; cq[nt][1] += v1 * v1;
            }
            if (r2 < M) {
                float v0 = acc[mt][nt][2] + b0;
                float v1 = acc[mt][nt][3] + b1;
                *(float2*)&C[(size_t)r2 * 128 + colb] = make_float2(v0, v1);
                cs[nt][0] += v0; cq[nt][0] += v0 * v0;
                cs[nt][1] += v1; cq[nt][1] += v1 * v1;
            }
        }
    }
#pragma unroll
    for (int nt = 0; nt < 4; nt++)
#pragma unroll
        for (int j = 0; j < 2; j++) {
            float s = cs[nt][j], q = cq[nt][j];
            s += __shfl_xor_sync(0xffffffffu, s, 4);
            s += __shfl_xor_sync(0xffffffffu, s, 8);
            s += __shfl_xor_sync(0xffffffffu, s, 16);
            q += __shfl_xor_sync(0xffffffffu, q, 4);
            q += __shfl_xor_sync(0xffffffffu, q, 8);
            q += __shfl_xor_sync(0xffffffffu, q, 16);
            if (gid == 0) {
                int col = wc * 32 + nt * 8 + 2 * tq + j;
                atomicAdd(&osum[col], s);
                atomicAdd(&osumsq[col], q);
            }
        }
}

// ------ fused BN + ReLU + graph pool: register-batched, 32 rows/block ------
__global__ void k_bnpool(const float* __restrict__ rep, float* __restrict__ h,
                         float* __restrict__ out, int off,
                         const float* __restrict__ gamma, const float* __restrict__ beta,
                         const int* __restrict__ gids, int slot, int write_h) {
    int c = threadIdx.x;                  // 128 threads = columns
    int r0 = blockIdx.x * BNP_ROWS;
    int nr = min(BNP_ROWS, NN - r0);
    const float invN = 1.0f / NN;
    float m = g_sum[slot][c] * invN;
    float v = g_sumsq[slot][c] * invN - m * m;
    float sc = gamma[c] * rsqrtf(v + BN_EPS);
    float sh = beta[c] - m * sc;

    float vals[BNP_ROWS];
    int gv[BNP_ROWS];
    if (nr == BNP_ROWS) {
#pragma unroll
        for (int i = 0; i < BNP_ROWS; i++) {
            vals[i] = rep[(size_t)(r0 + i) * DHF + c];
            gv[i] = gids[r0 + i];
        }
#pragma unroll
        for (int i = 0; i < BNP_ROWS; i++)
            vals[i] = fmaxf(vals[i] * sc + sh, 0.f);
        if (write_h) {
#pragma unroll
            for (int i = 0; i < BNP_ROWS; i++)
                h[(size_t)(r0 + i) * DHF + c] = vals[i];
        }
    } else {
        for (int i = 0; i < nr; i++) {
            vals[i] = rep[(size_t)(r0 + i) * DHF + c];
            gv[i] = gids[r0 + i];
        }
        for (int i = 0; i < nr; i++) {
            vals[i] = fmaxf(vals[i] * sc + sh, 0.f);
            if (write_h) h[(size_t)(r0 + i) * DHF + c] = vals[i];
        }
    }

    int curg = gv[0];
    float acc = 0.f;
    for (int i = 0; i < nr; i++) {
        if (gv[i] != curg) {
            atomicAdd(&out[(size_t)curg * OUTW + off + c], acc);
            acc = 0.f;
            curg = gv[i];
        }
        acc += vals[i];
    }
    atomicAdd(&out[(size_t)curg * OUTW + off + c], acc);
}

// register-batched pooling of raw x (D=200) into out[:, 0:200]
__global__ void k_poolx(const float* __restrict__ src, float* __restrict__ out,
                        const int* __restrict__ gids) {
    int c = threadIdx.x;                  // 256 threads, guard to 200
    if (c >= DINF) return;
    int r0 = blockIdx.x * BNP_ROWS;
    int nr = min(BNP_ROWS, NN - r0);

    float vals[BNP_ROWS];
    int gv[BNP_ROWS];
    if (nr == BNP_ROWS) {
#pragma unroll
        for (int i = 0; i < BNP_ROWS; i++) {
            vals[i] = src[(size_t)(r0 + i) * DINF + c];
            gv[i] = gids[r0 + i];
        }
    } else {
        for (int i = 0; i < nr; i++) {
            vals[i] = src[(size_t)(r0 + i) * DINF + c];
            gv[i] = gids[r0 + i];
        }
    }

    int curg = gv[0];
    float acc = 0.f;
    for (int i = 0; i < nr; i++) {
        if (gv[i] != curg) {
            atomicAdd(&out[(size_t)curg * OUTW + c], acc);
            acc = 0.f;
            curg = gv[i];
        }
        acc += vals[i];
    }
    atomicAdd(&out[(size_t)curg * OUTW + c], acc);
}

// ---------------- launch ---------------------------------------------------
extern "C" void kernel_launch(void* const* d_in, const int* in_sizes, int n_in,
                              void* d_out, int out_size) {
    const float* x     = (const float*)d_in[0];
    const int*   erow  = (const int*)d_in[1];
    const int*   ecol  = (const int*)d_in[2];
    const int*   gid   = (const int*)d_in[3];
    const float* eps   = (const float*)d_in[4];
    const float* w1_0  = (const float*)d_in[5];
    const float* b1_0  = (const float*)d_in[6];
    const float* g1_0  = (const float*)d_in[7];
    const float* be1_0 = (const float*)d_in[8];
    const float* w2_0  = (const float*)d_in[9];
    const float* b2_0  = (const float*)d_in[10];
    const float* gbn_0 = (const float*)d_in[11];
    const float* bbn_0 = (const float*)d_in[12];
    const float* w1_r  = (const float*)d_in[13];
    const float* b1_r  = (const float*)d_in[14];
    const float* g1_r  = (const float*)d_in[15];
    const float* be1_r = (const float*)d_in[16];
    const float* w2_r  = (const float*)d_in[17];
    const float* b2_r  = (const float*)d_in[18];
    const float* gbn_r = (const float*)d_in[19];
    const float* bbn_r = (const float*)d_in[20];
    float* out = (float*)d_out;

    int E = in_sizes[1];

    float *mid, *rep, *h, *sumb, *sumsqb;
    uint4 *apk;
    uint2 *wpk;
    cudaGetSymbolAddress((void**)&apk,    g_apk);
    cudaGetSymbolAddress((void**)&mid,    g_mid);
    cudaGetSymbolAddress((void**)&rep,    g_rep);
    cudaGetSymbolAddress((void**)&h,      g_h);
    cudaGetSymbolAddress((void**)&sumb,   g_sum);
    cudaGetSymbolAddress((void**)&sumsqb, g_sumsq);
    cudaGetSymbolAddress((void**)&wpk,    g_wpk);

    const int scan_smem = (NN + 1024) * (int)sizeof(int);
    cudaFuncSetAttribute(k_scan_big, cudaFuncAttributeMaxDynamicSharedMemorySize, scan_smem);

    k_packw<<<WPAIRS, DHF>>>(w1_0, w2_0, w1_r, w2_r);     // + zero hist counters
    k_hist<<<(E + 255) / 256, 256>>>(erow, E);
    k_scan_big<<<1, 1024, scan_smem>>>(out, out_size);    // + zero cursors/stats/out
    k_scatter<<<(E + 255) / 256, 256>>>(erow, ecol, E);

    const int spmm_blocks = (NN + 7) / 8;
    const int gemm_blocks = (NN + 127) / 128;
    const int pool_blocks = (NN + BNP_ROWS - 1) / BNP_ROWS;

    const int woff_g1[NLAY] = {0, 164, 228, 292};
    const int woff_g2[NLAY] = {100, 356, 420, 484};

    for (int l = 0; l < NLAY; l++) {
        const float *ba, *ga, *bea, *bb, *gb, *bbb;
        int K1;
        if (l == 0) {
            k_spmm<DINF / 4><<<spmm_blocks, 256>>>(x, apk, eps, 0);
            K1 = DINF;
            ba = b1_0; ga = g1_0; bea = be1_0;
            bb = b2_0; gb = gbn_0; bbb = bbn_0;
        } else {
            k_spmm<DHF / 4><<<spmm_blocks, 256>>>(h, apk, eps, l);
            K1 = DHF;
            int o1 = (l - 1) * DHF;
            ba = b1_r + o1; ga = g1_r + o1; bea = be1_r + o1;
            bb = b2_r + o1; gb = gbn_r + o1; bbb = bbn_r + o1;
        }

        k_gemm_tc<1><<<gemm_blocks, 512>>>(nullptr, apk, wpk + woff_g1[l] * DHF,
                                           ba, mid, NN, K1,
                                           nullptr, nullptr, nullptr, nullptr,
                                           sumb + (2 * l) * DHF, sumsqb + (2 * l) * DHF);
        k_gemm_tc<0><<<gemm_blocks, 512>>>(mid, nullptr, wpk + woff_g2[l] * DHF,
                                           bb, rep, NN, DHF,
                                           ga, bea, sumb + (2 * l) * DHF, sumsqb + (2 * l) * DHF,
                                           sumb + (2 * l + 1) * DHF, sumsqb + (2 * l + 1) * DHF);

        k_bnpool<<<pool_blocks, DHF>>>(rep, h, out, DINF + l * DHF, gb, bbb,
                                       gid, 2 * l + 1, (l < NLAY - 1) ? 1 : 0);
    }

    k_poolx<<<pool_blocks, 256>>>(x, out, gid);
}

// round 10
// speedup vs baseline: 1.2186x; 1.1108x over previous
#include <cuda_runtime.h>
#include <cuda_bf16.h>
#include <cstdint>

// Problem constants (fixed-shape problem)
#define NN      50000
#define EE_MAX  800000
#define GG      128
#define DINF    200
#define DHF     128
#define NLAY    4
#define BN_EPS  1e-5f
#define OUTW    (DINF + NLAY * DHF)   // 712
#define BNP_ROWS 32
#define WPAIRS  548
#define APK_W   50
#define GEMM_SMEM_PAD 36864           // forces smem-occ = 3 on the GEMM

// ---------------- scratch (device globals; no allocation allowed) ----------
__device__ uint4 g_apk    [NN * APK_W];
__device__ float g_mid    [NN * DHF];
__device__ float g_rep    [NN * DHF];
__device__ float g_h      [NN * DHF];
__device__ int   g_cnt    [2 * NN];
__device__ int   g_rowptr [NN + 1];
__device__ int   g_colidx [EE_MAX];
__device__ float g_sum    [2 * NLAY][DHF];
__device__ float g_sumsq  [2 * NLAY][DHF];
__device__ uint2 g_wpk    [WPAIRS * DHF];

// ---------------- bf16 hi/lo split helpers ---------------------------------
__device__ __forceinline__ uint32_t pack_bf16(float v0, float v1, float& rem0, float& rem1) {
    __nv_bfloat16 h0 = __float2bfloat16(v0);
    __nv_bfloat16 h1 = __float2bfloat16(v1);
    rem0 = v0 - __bfloat162float(h0);
    rem1 = v1 - __bfloat162float(h1);
    return ((uint32_t)__bfloat16_as_ushort(h1) << 16) | (uint32_t)__bfloat16_as_ushort(h0);
}
__device__ __forceinline__ uint32_t pack_bf16_rn(float v0, float v1) {
    __nv_bfloat162 p = __floats2bfloat162_rn(v0, v1);
    return *(uint32_t*)&p;
}

// -------- weight prepack + hist-counter zeroing + out zeroing --------------
__global__ void k_packw(const float* __restrict__ w1_0, const float* __restrict__ w2_0,
                        const float* __restrict__ w1_r, const float* __restrict__ w2_r,
                        float* __restrict__ out, int out_n) {
    int b = blockIdx.x;
    int c = threadIdx.x;
    int gtid = b * DHF + c;
    for (int i = gtid; i < NN; i += WPAIRS * DHF) g_cnt[i] = 0;
    for (int i = gtid; i < out_n; i += WPAIRS * DHF) out[i] = 0.f;

    const float* src;
    int kp;
    if (b < 100)      { src = w1_0; kp = b; }
    else if (b < 164) { src = w2_0; kp = b - 100; }
    else {
        int r = b - 164;
        if (r < 192) { src = w1_r + (r / 64) * DHF * DHF; kp = r % 64; }
        else { r -= 192; src = w2_r + (r / 64) * DHF * DHF; kp = r % 64; }
    }
    float v0 = src[(size_t)(2 * kp) * DHF + c];
    float v1 = src[(size_t)(2 * kp + 1) * DHF + c];
    float r0, r1;
    uint32_t hi = pack_bf16(v0, v1, r0, r1);
    uint32_t lo = pack_bf16_rn(r0, r1);
    g_wpk[b * DHF + c] = make_uint2(hi, lo);
}

// ---------------- CSR build ------------------------------------------------
__global__ void k_hist(const int* __restrict__ erow, int E) {
    int e = blockIdx.x * blockDim.x + threadIdx.x;
    if (e < E) atomicAdd(&g_cnt[erow[e]], 1);
}

__global__ void k_scan_big() {
    extern __shared__ int sc[];
    int* part = sc + NN;
    const int T = 1024;
    int t = threadIdx.x;

    if (t < DHF) {
        for (int l = 0; l < 2 * NLAY; l++) { g_sum[l][t] = 0.f; g_sumsq[l][t] = 0.f; }
    }
    for (int i = t; i < NN; i += T) {
        sc[i] = g_cnt[i];
        g_cnt[NN + i] = 0;
    }
    __syncthreads();

    const int C = (NN + T - 1) / T;
    int base = t * C;
    int s = 0;
    for (int j = 0; j < C; j++) {
        int i = base + j;
        if (i < NN) s += sc[i];
    }
    part[t] = s;
    __syncthreads();
    for (int off = 1; off < T; off <<= 1) {
        int v = (t >= off) ? part[t - off] : 0;
        __syncthreads();
        part[t] += v;
        __syncthreads();
    }
    int pre = (t > 0) ? part[t - 1] : 0;
    for (int j = 0; j < C; j++) {
        int i = base + j;
        if (i < NN) {
            int c = sc[i];
            sc[i] = pre;
            pre += c;
        }
    }
    __syncthreads();
    for (int i = t; i < NN; i += T) g_rowptr[i] = sc[i];
    if (t == T - 1) g_rowptr[NN] = pre;
}

__global__ void k_scatter(const int* __restrict__ erow, const int* __restrict__ ecol, int E) {
    int e = blockIdx.x * blockDim.x + threadIdx.x;
    if (e < E) {
        int r = erow[e];
        int p = g_rowptr[r] + atomicAdd(&g_cnt[NN + r], 1);
        g_colidx[p] = ecol[e];
    }
}

// ---------------- SpMM (pull / CSR), 4-edge unroll, packed-bf16 output -----
template <int D4>
__global__ void k_spmm(const float* __restrict__ hin, uint4* __restrict__ pout,
                       const float* __restrict__ epsv, int li) {
    int wid  = blockIdx.x * 8 + (threadIdx.x >> 5);
    int lane = threadIdx.x & 31;
    if (wid >= NN) return;
    const int S = (D4 + 31) / 32;
    float se = 1.0f + epsv[li];

    const float4* selfr = (const float4*)hin + (size_t)wid * D4;
    float4 acc[S];
#pragma unroll
    for (int s = 0; s < S; s++) {
        int j = lane + 32 * s;
        if (j < D4) {
            float4 v = selfr[j];
            acc[s] = make_float4(v.x * se, v.y * se, v.z * se, v.w * se);
        } else acc[s] = make_float4(0.f, 0.f, 0.f, 0.f);
    }
    int e0 = g_rowptr[wid], e1 = g_rowptr[wid + 1];
    int e = e0;
    for (; e + 4 <= e1; e += 4) {
        int c0 = g_colidx[e], c1 = g_colidx[e + 1];
        int c2 = g_colidx[e + 2], c3 = g_colidx[e + 3];
        const float4* r0 = (const float4*)hin + (size_t)c0 * D4;
        const float4* r1 = (const float4*)hin + (size_t)c1 * D4;
        const float4* r2 = (const float4*)hin + (size_t)c2 * D4;
        const float4* r3 = (const float4*)hin + (size_t)c3 * D4;
#pragma unroll
        for (int s = 0; s < S; s++) {
            int j = lane + 32 * s;
            if (j < D4) {
                float4 v0 = r0[j], v1 = r1[j], v2 = r2[j], v3 = r3[j];
                acc[s].x += (v0.x + v1.x) + (v2.x + v3.x);
                acc[s].y += (v0.y + v1.y) + (v2.y + v3.y);
                acc[s].z += (v0.z + v1.z) + (v2.z + v3.z);
                acc[s].w += (v0.w + v1.w) + (v2.w + v3.w);
            }
        }
    }
    for (; e < e1; e++) {
        int c = g_colidx[e];
        const float4* r = (const float4*)hin + (size_t)c * D4;
#pragma unroll
        for (int s = 0; s < S; s++) {
            int j = lane + 32 * s;
            if (j < D4) {
                float4 v = r[j];
                acc[s].x += v.x; acc[s].y += v.y; acc[s].z += v.z; acc[s].w += v.w;
            }
        }
    }
    uint4* o = pout + (size_t)wid * D4;
#pragma unroll
    for (int s = 0; s < S; s++) {
        int j = lane + 32 * s;
        if (j < D4) {
            float r0, r1, r2, r3;
            uint32_t h01 = pack_bf16(acc[s].x, acc[s].y, r0, r1);
            uint32_t h23 = pack_bf16(acc[s].z, acc[s].w, r2, r3);
            o[j] = make_uint4(h01, h23, pack_bf16_rn(r0, r1), pack_bf16_rn(r2, r3));
        }
    }
}

// ---------------- 3xBF16 tensor-core GEMM: 64-row tiles, 256 thr, occ 3 ----
__device__ __forceinline__ void mma16(float* c, const uint32_t* a, const uint32_t* b) {
    asm volatile(
        "mma.sync.aligned.m16n8k16.row.col.f32.bf16.bf16.f32 "
        "{%0,%1,%2,%3}, {%4,%5,%6,%7}, {%8,%9}, {%0,%1,%2,%3};"
        : "+f"(c[0]), "+f"(c[1]), "+f"(c[2]), "+f"(c[3])
        : "r"(a[0]), "r"(a[1]), "r"(a[2]), "r"(a[3]), "r"(b[0]), "r"(b[1]));
}

template <int PACKED>
__global__ __launch_bounds__(256, 3)
void k_gemm_tc(const float* __restrict__ A, const uint4* __restrict__ Apk,
               const uint2* __restrict__ wpk,
               const float* __restrict__ bias, float* __restrict__ C,
               int M, int K,
               const float* __restrict__ bnga, const float* __restrict__ bnbe,
               const float* __restrict__ psum, const float* __restrict__ psq,
               float* __restrict__ osum, float* __restrict__ osumsq) {
    __shared__ uint32_t ash[2][8][72], asl[2][8][72];   // 64-row A tile (+pad 8)
    __shared__ uint32_t wsh[2][8][136], wsl[2][8][136]; // 128-col W tile
    __shared__ float strs[DHF], strh[DHF];
    extern __shared__ char occ_pad[];                   // occupancy pin only

    const int tid  = threadIdx.x;
    const int lane = tid & 31;
    const int wid  = tid >> 5;        // 0..7
    const int wr   = wid >> 2;        // 0..1 (row group of 32)
    const int wc   = wid & 3;         // 0..3 (col group of 32)
    const int gid  = lane >> 2;
    const int tq   = lane & 3;
    const int row0 = blockIdx.x * 64;

    const int arA = tid & 63;         // A staging row
    const int kgA = tid >> 6;         // 0..3 -> k group of 4
    const int arW = tid & 127;        // W staging column
    const int kgW = tid >> 7;         // 0..1

    const int KP  = K >> 1;
    const int KP4 = K >> 2;

    if (!PACKED) {
        if (bnga && tid < DHF) {
            const float invN = 1.0f / NN;
            float m = psum[tid] * invN;
            float v = psq[tid] * invN - m * m;
            float rs = rsqrtf(v + BN_EPS);
            float sc = bnga[tid] * rs;
            strs[tid] = sc;
            strh[tid] = bnbe[tid] - m * sc;
        }
        __syncthreads();
    }

    float acc[2][4][4];
#pragma unroll
    for (int mt = 0; mt < 2; mt++)
#pragma unroll
        for (int nt = 0; nt < 4; nt++)
#pragma unroll
            for (int j = 0; j < 4; j++) acc[mt][nt][j] = 0.f;

    const int T = (K + 15) >> 4;
    const int grA = row0 + arA;
    const bool rokA = (grA < M);

    float4 va;
    uint4 pa;
    uint2 wk[4];

    auto prefetch = [&](int t) {
        if (PACKED) {
            int gp = t * 4 + kgA;
            pa = make_uint4(0u, 0u, 0u, 0u);
            if (rokA && gp < KP4) pa = Apk[(size_t)grA * KP4 + gp];
        } else {
            int gk0 = t * 16 + 4 * kgA;
            va = make_float4(0.f, 0.f, 0.f, 0.f);
            if (rokA && gk0 < K) va = *(const float4*)&A[(size_t)grA * K + gk0];
        }
#pragma unroll
        for (int j = 0; j < 4; j++) {
            int kp = t * 8 + kgW + 2 * j;
            wk[j] = (kp < KP) ? wpk[kp * DHF + arW] : make_uint2(0u, 0u);
        }
    };

    auto stage = [&](int d, int k0) {
        if (PACKED) {
            ash[d][2 * kgA][arA]     = pa.x;
            ash[d][2 * kgA + 1][arA] = pa.y;
            asl[d][2 * kgA][arA]     = pa.z;
            asl[d][2 * kgA + 1][arA] = pa.w;
        } else {
            float a4[4] = {va.x, va.y, va.z, va.w};
            if (bnga && rokA) {
#pragma unroll
                for (int j = 0; j < 4; j++) {
                    int gk = k0 + 4 * kgA + j;
                    a4[j] = (gk < K) ? fmaxf(a4[j] * strs[gk] + strh[gk], 0.f) : 0.f;
                }
            }
#pragma unroll
            for (int p = 0; p < 2; p++) {
                float r0f, r1f;
                ash[d][2 * kgA + p][arA] = pack_bf16(a4[2 * p], a4[2 * p + 1], r0f, r1f);
                asl[d][2 * kgA + p][arA] = pack_bf16_rn(r0f, r1f);
            }
        }
#pragma unroll
        for (int j = 0; j < 4; j++) {
            wsh[d][kgW + 2 * j][arW] = wk[j].x;
            wsl[d][kgW + 2 * j][arW] = wk[j].y;
        }
    };

    prefetch(0);
    stage(0, 0);
    __syncthreads();

    for (int t = 0; t < T; t++) {
        const int cur = t & 1;
        if (t + 1 < T) prefetch(t + 1);

        {
            uint32_t bh[4][2], bl[4][2];
#pragma unroll
            for (int nt = 0; nt < 4; nt++) {
                int col = wc * 32 + nt * 8 + gid;
                bh[nt][0] = wsh[cur][tq][col];
                bh[nt][1] = wsh[cur][tq + 4][col];
                bl[nt][0] = wsl[cur][tq][col];
                bl[nt][1] = wsl[cur][tq + 4][col];
            }
#pragma unroll
            for (int mt = 0; mt < 2; mt++) {
                int r0 = wr * 32 + mt * 16;
                uint32_t ah[4], al[4];
                ah[0] = ash[cur][tq][r0 + gid];
                ah[1] = ash[cur][tq][r0 + gid + 8];
                ah[2] = ash[cur][tq + 4][r0 + gid];
                ah[3] = ash[cur][tq + 4][r0 + gid + 8];
                al[0] = asl[cur][tq][r0 + gid];
                al[1] = asl[cur][tq][r0 + gid + 8];
                al[2] = asl[cur][tq + 4][r0 + gid];
                al[3] = asl[cur][tq + 4][r0 + gid + 8];
#pragma unroll
                for (int nt = 0; nt < 4; nt++) {
                    mma16(acc[mt][nt], ah, bh[nt]);
                    mma16(acc[mt][nt], al, bh[nt]);
                    mma16(acc[mt][nt], ah, bl[nt]);
                }
            }
        }

        if (t + 1 < T) stage((t + 1) & 1, (t + 1) * 16);
        __syncthreads();
    }

    // ---- epilogue: bias, store, column stats ----
    float cs[4][2], cq[4][2];
#pragma unroll
    for (int nt = 0; nt < 4; nt++)
#pragma unroll
        for (int j = 0; j < 2; j++) { cs[nt][j] = 0.f; cq[nt][j] = 0.f; }

#pragma unroll
    for (int mt = 0; mt < 2; mt++) {
        int rbase = row0 + wr * 32 + mt * 16;
#pragma unroll
        for (int nt = 0; nt < 4; nt++) {
            int colb = wc * 32 + nt * 8 + 2 * tq;
            float b0 = bias[colb], b1 = bias[colb + 1];
            int r1 = rbase + gid;
            int r2 = rbase + gid + 8;
            if (r1 < M) {
                float v0 = acc[mt][nt][0] + b0;
                float v1 = acc[mt][nt][1] + b1;
                *(float2*)&C[(size_t)r1 * 128 + colb] = make_float2(v0, v1);
                cs[nt][0] += v0; cq[nt][0] += v0 * v0;
                cs[nt][1] += v1; cq[nt][1] += v1 * v1;
            }
            if (r2 < M) {
                float v0 = acc[mt][nt][2] + b0;
                float v1 = acc[mt][nt][3] + b1;
                *(float2*)&C[(size_t)r2 * 128 + colb] = make_float2(v0, v1);
                cs[nt][0] += v0; cq[nt][0] += v0 * v0;
                cs[nt][1] += v1; cq[nt][1] += v1 * v1;
            }
        }
    }
#pragma unroll
    for (int nt = 0; nt < 4; nt++)
#pragma unroll
        for (int j = 0; j < 2; j++) {
            float s = cs[nt][j], q = cq[nt][j];
            s += __shfl_xor_sync(0xffffffffu, s, 4);
            s += __shfl_xor_sync(0xffffffffu, s, 8);
            s += __shfl_xor_sync(0xffffffffu, s, 16);
            q += __shfl_xor_sync(0xffffffffu, q, 4);
            q += __shfl_xor_sync(0xffffffffu, q, 8);
            q += __shfl_xor_sync(0xffffffffu, q, 16);
            if (gid == 0) {
                int col = wc * 32 + nt * 8 + 2 * tq + j;
                atomicAdd(&osum[col], s);
                atomicAdd(&osumsq[col], q);
            }
        }
}

// ------ fused BN + ReLU + graph pool: register-batched, 32 rows/block ------
__global__ void k_bnpool(const float* __restrict__ rep, float* __restrict__ h,
                         float* __restrict__ out, int off,
                         const float* __restrict__ gamma, const float* __restrict__ beta,
                         const int* __restrict__ gids, int slot, int write_h) {
    int c = threadIdx.x;
    int r0 = blockIdx.x * BNP_ROWS;
    int nr = min(BNP_ROWS, NN - r0);
    const float invN = 1.0f / NN;
    float m = g_sum[slot][c] * invN;
    float v = g_sumsq[slot][c] * invN - m * m;
    float sc = gamma[c] * rsqrtf(v + BN_EPS);
    float sh = beta[c] - m * sc;

    float vals[BNP_ROWS];
    int gv[BNP_ROWS];
    if (nr == BNP_ROWS) {
#pragma unroll
        for (int i = 0; i < BNP_ROWS; i++) {
            vals[i] = rep[(size_t)(r0 + i) * DHF + c];
            gv[i] = gids[r0 + i];
        }
#pragma unroll
        for (int i = 0; i < BNP_ROWS; i++)
            vals[i] = fmaxf(vals[i] * sc + sh, 0.f);
        if (write_h) {
#pragma unroll
            for (int i = 0; i < BNP_ROWS; i++)
                h[(size_t)(r0 + i) * DHF + c] = vals[i];
        }
    } else {
        for (int i = 0; i < nr; i++) {
            vals[i] = rep[(size_t)(r0 + i) * DHF + c];
            gv[i] = gids[r0 + i];
        }
        for (int i = 0; i < nr; i++) {
            vals[i] = fmaxf(vals[i] * sc + sh, 0.f);
            if (write_h) h[(size_t)(r0 + i) * DHF + c] = vals[i];
        }
    }

    int curg = gv[0];
    float acc = 0.f;
    for (int i = 0; i < nr; i++) {
        if (gv[i] != curg) {
            atomicAdd(&out[(size_t)curg * OUTW + off + c], acc);
            acc = 0.f;
            curg = gv[i];
        }
        acc += vals[i];
    }
    atomicAdd(&out[(size_t)curg * OUTW + off + c], acc);
}

__global__ void k_poolx(const float* __restrict__ src, float* __restrict__ out,
                        const int* __restrict__ gids) {
    int c = threadIdx.x;
    if (c >= DINF) return;
    int r0 = blockIdx.x * BNP_ROWS;
    int nr = min(BNP_ROWS, NN - r0);

    float vals[BNP_ROWS];
    int gv[BNP_ROWS];
    if (nr == BNP_ROWS) {
#pragma unroll
        for (int i = 0; i < BNP_ROWS; i++) {
            vals[i] = src[(size_t)(r0 + i) * DINF + c];
            gv[i] = gids[r0 + i];
        }
    } else {
        for (int i = 0; i < nr; i++) {
            vals[i] = src[(size_t)(r0 + i) * DINF + c];
            gv[i] = gids[r0 + i];
        }
    }

    int curg = gv[0];
    float acc = 0.f;
    for (int i = 0; i < nr; i++) {
        if (gv[i] != curg) {
            atomicAdd(&out[(size_t)curg * OUTW + c], acc);
            acc = 0.f;
            curg = gv[i];
        }
        acc += vals[i];
    }
    atomicAdd(&out[(size_t)curg * OUTW + c], acc);
}

// ---------------- launch ---------------------------------------------------
extern "C" void kernel_launch(void* const* d_in, const int* in_sizes, int n_in,
                              void* d_out, int out_size) {
    const float* x     = (const float*)d_in[0];
    const int*   erow  = (const int*)d_in[1];
    const int*   ecol  = (const int*)d_in[2];
    const int*   gid   = (const int*)d_in[3];
    const float* eps   = (const float*)d_in[4];
    const float* w1_0  = (const float*)d_in[5];
    const float* b1_0  = (const float*)d_in[6];
    const float* g1_0  = (const float*)d_in[7];
    const float* be1_0 = (const float*)d_in[8];
    const float* w2_0  = (const float*)d_in[9];
    const float* b2_0  = (const float*)d_in[10];
    const float* gbn_0 = (const float*)d_in[11];
    const float* bbn_0 = (const float*)d_in[12];
    const float* w1_r  = (const float*)d_in[13];
    const float* b1_r  = (const float*)d_in[14];
    const float* g1_r  = (const float*)d_in[15];
    const float* be1_r = (const float*)d_in[16];
    const float* w2_r  = (const float*)d_in[17];
    const float* b2_r  = (const float*)d_in[18];
    const float* gbn_r = (const float*)d_in[19];
    const float* bbn_r = (const float*)d_in[20];
    float* out = (float*)d_out;

    int E = in_sizes[1];

    float *mid, *rep, *h, *sumb, *sumsqb;
    uint4 *apk;
    uint2 *wpk;
    cudaGetSymbolAddress((void**)&apk,    g_apk);
    cudaGetSymbolAddress((void**)&mid,    g_mid);
    cudaGetSymbolAddress((void**)&rep,    g_rep);
    cudaGetSymbolAddress((void**)&h,      g_h);
    cudaGetSymbolAddress((void**)&sumb,   g_sum);
    cudaGetSymbolAddress((void**)&sumsqb, g_sumsq);
    cudaGetSymbolAddress((void**)&wpk,    g_wpk);

    const int scan_smem = (NN + 1024) * (int)sizeof(int);
    cudaFuncSetAttribute(k_scan_big, cudaFuncAttributeMaxDynamicSharedMemorySize, scan_smem);
    cudaFuncSetAttribute(k_gemm_tc<0>, cudaFuncAttributeMaxDynamicSharedMemorySize, GEMM_SMEM_PAD);
    cudaFuncSetAttribute(k_gemm_tc<1>, cudaFuncAttributeMaxDynamicSharedMemorySize, GEMM_SMEM_PAD);

    k_packw<<<WPAIRS, DHF>>>(w1_0, w2_0, w1_r, w2_r, out, out_size);
    k_hist<<<(E + 255) / 256, 256>>>(erow, E);
    k_scan_big<<<1, 1024, scan_smem>>>();
    k_scatter<<<(E + 255) / 256, 256>>>(erow, ecol, E);

    const int spmm_blocks = (NN + 7) / 8;
    const int gemm_blocks = (NN + 63) / 64;
    const int pool_blocks = (NN + BNP_ROWS - 1) / BNP_ROWS;

    const int woff_g1[NLAY] = {0, 164, 228, 292};
    const int woff_g2[NLAY] = {100, 356, 420, 484};

    for (int l = 0; l < NLAY; l++) {
        const float *ba, *ga, *bea, *bb, *gb, *bbb;
        int K1;
        if (l == 0) {
            k_spmm<DINF / 4><<<spmm_blocks, 256>>>(x, apk, eps, 0);
            K1 = DINF;
            ba = b1_0; ga = g1_0; bea = be1_0;
            bb = b2_0; gb = gbn_0; bbb = bbn_0;
        } else {
            k_spmm<DHF / 4><<<spmm_blocks, 256>>>(h, apk, eps, l);
            K1 = DHF;
            int o1 = (l - 1) * DHF;
            ba = b1_r + o1; ga = g1_r + o1; bea = be1_r + o1;
            bb = b2_r + o1; gb = gbn_r + o1; bbb = bbn_r + o1;
        }

        k_gemm_tc<1><<<gemm_blocks, 256, GEMM_SMEM_PAD>>>(
            nullptr, apk, wpk + woff_g1[l] * DHF, ba, mid, NN, K1,
            nullptr, nullptr, nullptr, nullptr,
            sumb + (2 * l) * DHF, sumsqb + (2 * l) * DHF);
        k_gemm_tc<0><<<gemm_blocks, 256, GEMM_SMEM_PAD>>>(
            mid, nullptr, wpk + woff_g2[l] * DHF, bb, rep, NN, DHF,
            ga, bea, sumb + (2 * l) * DHF, sumsqb + (2 * l) * DHF,
            sumb + (2 * l + 1) * DHF, sumsqb + (2 * l + 1) * DHF);

        k_bnpool<<<pool_blocks, DHF>>>(rep, h, out, DINF + l * DHF, gb, bbb,
                                       gid, 2 * l + 1, (l < NLAY - 1) ? 1 : 0);
    }

    k_poolx<<<pool_blocks, 256>>>(x, out, gid);
}

// round 12
// speedup vs baseline: 1.2444x; 1.0211x over previous
#include <cuda_runtime.h>
#include <cuda_fp16.h>
#include <cstdint>

// Problem constants (fixed-shape problem)
#define NN      50000
#define EE_MAX  800000
#define GG      128
#define DINF    200
#define DHF     128
#define NLAY    4
#define BN_EPS  1e-5f
#define OUTW    (DINF + NLAY * DHF)   // 712
#define BNP_ROWS 32
#define WPAIRS  548
#define APK_W   50
#define GEMM_SMEM_PAD 36864           // occupancy pin on the GEMM
#define GEMM_GRID 444                 // 148 SMs x occ 3 (persistent)

// ---------------- scratch (device globals; no allocation allowed) ----------
__device__ uint4    g_apk    [NN * APK_W];
__device__ float    g_mid    [NN * DHF];
__device__ float    g_rep    [NN * DHF];
__device__ float    g_h      [NN * DHF];
__device__ int      g_cnt    [2 * NN];
__device__ int      g_rowptr [NN + 1];
__device__ int      g_colidx [EE_MAX];
__device__ float    g_sum    [2 * NLAY][DHF];
__device__ float    g_sumsq  [2 * NLAY][DHF];
__device__ uint32_t g_wpk    [WPAIRS * DHF];   // fp16x2 of W pair-rows
__device__ int      g_qctr   [16];             // persistent-GEMM work queues

// ---------------- fp16 hi/lo split helpers ---------------------------------
__device__ __forceinline__ uint32_t pack_f16(float v0, float v1, float& rem0, float& rem1) {
    __half h0 = __float2half_rn(v0);
    __half h1 = __float2half_rn(v1);
    rem0 = v0 - __half2float(h0);
    rem1 = v1 - __half2float(h1);
    return ((uint32_t)__half_as_ushort(h1) << 16) | (uint32_t)__half_as_ushort(h0);
}
__device__ __forceinline__ uint32_t pack_f16_rn(float v0, float v1) {
    __half2 p = __floats2half2_rn(v0, v1);   // .x = v0 (low half)
    return *(uint32_t*)&p;
}

// -------- weight prepack (fp16) + hist zero + out zero ---------------------
__global__ void k_packw(const float* __restrict__ w1_0, const float* __restrict__ w2_0,
                        const float* __restrict__ w1_r, const float* __restrict__ w2_r,
                        float* __restrict__ out, int out_n) {
    int b = blockIdx.x;
    int c = threadIdx.x;
    int gtid = b * DHF + c;
    for (int i = gtid; i < NN; i += WPAIRS * DHF) g_cnt[i] = 0;
    for (int i = gtid; i < out_n; i += WPAIRS * DHF) out[i] = 0.f;

    const float* src;
    int kp;
    if (b < 100)      { src = w1_0; kp = b; }
    else if (b < 164) { src = w2_0; kp = b - 100; }
    else {
        int r = b - 164;
        if (r < 192) { src = w1_r + (r / 64) * DHF * DHF; kp = r % 64; }
        else { r -= 192; src = w2_r + (r / 64) * DHF * DHF; kp = r % 64; }
    }
    float v0 = src[(size_t)(2 * kp) * DHF + c];
    float v1 = src[(size_t)(2 * kp + 1) * DHF + c];
    g_wpk[b * DHF + c] = pack_f16_rn(v0, v1);
}

// ---------------- CSR build ------------------------------------------------
__global__ void k_hist(const int* __restrict__ erow, int E) {
    int e = blockIdx.x * blockDim.x + threadIdx.x;
    if (e < E) atomicAdd(&g_cnt[erow[e]], 1);
}

__global__ void k_scan_big() {
    extern __shared__ int sc[];
    int* part = sc + NN;
    const int T = 1024;
    int t = threadIdx.x;

    if (t < DHF) {
        for (int l = 0; l < 2 * NLAY; l++) { g_sum[l][t] = 0.f; g_sumsq[l][t] = 0.f; }
    }
    if (t < 16) g_qctr[t] = 0;
    for (int i = t; i < NN; i += T) {
        sc[i] = g_cnt[i];
        g_cnt[NN + i] = 0;
    }
    __syncthreads();

    const int C = (NN + T - 1) / T;
    int base = t * C;
    int s = 0;
    for (int j = 0; j < C; j++) {
        int i = base + j;
        if (i < NN) s += sc[i];
    }
    part[t] = s;
    __syncthreads();
    for (int off = 1; off < T; off <<= 1) {
        int v = (t >= off) ? part[t - off] : 0;
        __syncthreads();
        part[t] += v;
        __syncthreads();
    }
    int pre = (t > 0) ? part[t - 1] : 0;
    for (int j = 0; j < C; j++) {
        int i = base + j;
        if (i < NN) {
            int c = sc[i];
            sc[i] = pre;
            pre += c;
        }
    }
    __syncthreads();
    for (int i = t; i < NN; i += T) g_rowptr[i] = sc[i];
    if (t == T - 1) g_rowptr[NN] = pre;
}

__global__ void k_scatter(const int* __restrict__ erow, const int* __restrict__ ecol, int E) {
    int e = blockIdx.x * blockDim.x + threadIdx.x;
    if (e < E) {
        int r = erow[e];
        int p = g_rowptr[r] + atomicAdd(&g_cnt[NN + r], 1);
        g_colidx[p] = ecol[e];
    }
}

// ---------------- SpMM (pull / CSR), 4-edge unroll, packed-fp16 output -----
template <int D4>
__global__ void k_spmm(const float* __restrict__ hin, uint4* __restrict__ pout,
                       const float* __restrict__ epsv, int li) {
    int wid  = blockIdx.x * 8 + (threadIdx.x >> 5);
    int lane = threadIdx.x & 31;
    if (wid >= NN) return;
    const int S = (D4 + 31) / 32;
    float se = 1.0f + epsv[li];

    const float4* selfr = (const float4*)hin + (size_t)wid * D4;
    float4 acc[S];
#pragma unroll
    for (int s = 0; s < S; s++) {
        int j = lane + 32 * s;
        if (j < D4) {
            float4 v = selfr[j];
            acc[s] = make_float4(v.x * se, v.y * se, v.z * se, v.w * se);
        } else acc[s] = make_float4(0.f, 0.f, 0.f, 0.f);
    }
    int e0 = g_rowptr[wid], e1 = g_rowptr[wid + 1];
    int e = e0;
    for (; e + 4 <= e1; e += 4) {
        int c0 = g_colidx[e], c1 = g_colidx[e + 1];
        int c2 = g_colidx[e + 2], c3 = g_colidx[e + 3];
        const float4* r0 = (const float4*)hin + (size_t)c0 * D4;
        const float4* r1 = (const float4*)hin + (size_t)c1 * D4;
        const float4* r2 = (const float4*)hin + (size_t)c2 * D4;
        const float4* r3 = (const float4*)hin + (size_t)c3 * D4;
#pragma unroll
        for (int s = 0; s < S; s++) {
            int j = lane + 32 * s;
            if (j < D4) {
                float4 v0 = r0[j], v1 = r1[j], v2 = r2[j], v3 = r3[j];
                acc[s].x += (v0.x + v1.x) + (v2.x + v3.x);
                acc[s].y += (v0.y + v1.y) + (v2.y + v3.y);
                acc[s].z += (v0.z + v1.z) + (v2.z + v3.z);
                acc[s].w += (v0.w + v1.w) + (v2.w + v3.w);
            }
        }
    }
    for (; e < e1; e++) {
        int c = g_colidx[e];
        const float4* r = (const float4*)hin + (size_t)c * D4;
#pragma unroll
        for (int s = 0; s < S; s++) {
            int j = lane + 32 * s;
            if (j < D4) {
                float4 v = r[j];
                acc[s].x += v.x; acc[s].y += v.y; acc[s].z += v.z; acc[s].w += v.w;
            }
        }
    }
    uint4* o = pout + (size_t)wid * D4;
#pragma unroll
    for (int s = 0; s < S; s++) {
        int j = lane + 32 * s;
        if (j < D4) {
            float r0, r1, r2, r3;
            uint32_t h01 = pack_f16(acc[s].x, acc[s].y, r0, r1);
            uint32_t h23 = pack_f16(acc[s].z, acc[s].w, r2, r3);
            o[j] = make_uint4(h01, h23, pack_f16_rn(r0, r1), pack_f16_rn(r2, r3));
        }
    }
}

// ------- 2-term fp16 tensor-core GEMM: persistent, work-queue, occ 3 -------
// C = A @ fp16(W) + bias, A split exactly (hiA+loA): mma(hiA,hiW)+mma(loA,hiW)
__device__ __forceinline__ void mma16(float* c, const uint32_t* a, const uint32_t* b) {
    asm volatile(
        "mma.sync.aligned.m16n8k16.row.col.f32.f16.f16.f32 "
        "{%0,%1,%2,%3}, {%4,%5,%6,%7}, {%8,%9}, {%0,%1,%2,%3};"
        : "+f"(c[0]), "+f"(c[1]), "+f"(c[2]), "+f"(c[3])
        : "r"(a[0]), "r"(a[1]), "r"(a[2]), "r"(a[3]), "r"(b[0]), "r"(b[1]));
}

template <int PACKED>
__global__ __launch_bounds__(256, 3)
void k_gemm_tc(const float* __restrict__ A, const uint4* __restrict__ Apk,
               const uint32_t* __restrict__ wpk,
               const float* __restrict__ bias, float* __restrict__ C,
               int M, int K, int ntiles, int qslot,
               const float* __restrict__ bnga, const float* __restrict__ bnbe,
               const float* __restrict__ psum, const float* __restrict__ psq,
               float* __restrict__ osum, float* __restrict__ osumsq) {
    __shared__ uint32_t ash[2][8][72], asl[2][8][72];   // 64-row A tile (hi/lo)
    __shared__ uint32_t wsh[2][8][136];                 // 128-col W tile
    __shared__ float strs[DHF], strh[DHF];
    __shared__ int s_tile;
    extern __shared__ char occ_pad[];                   // occupancy pin only

    const int tid  = threadIdx.x;
    const int lane = tid & 31;
    const int wid  = tid >> 5;        // 0..7
    const int wr   = wid >> 2;        // 0..1
    const int wc   = wid & 3;         // 0..3
    const int gid  = lane >> 2;
    const int tq   = lane & 3;

    const int arA = tid & 63;
    const int kgA = tid >> 6;         // 0..3
    const int arW = tid & 127;
    const int kgW = tid >> 7;         // 0..1

    const int KP  = K >> 1;
    const int KP4 = K >> 2;
    const int T   = (K + 15) >> 4;

    if (!PACKED) {
        if (bnga && tid < DHF) {
            const float invN = 1.0f / NN;
            float m = psum[tid] * invN;
            float v = psq[tid] * invN - m * m;
            float rs = rsqrtf(v + BN_EPS);
            float sc = bnga[tid] * rs;
            strs[tid] = sc;
            strh[tid] = bnbe[tid] - m * sc;
        }
        __syncthreads();
    }

    while (true) {
        if (tid == 0) s_tile = atomicAdd(&g_qctr[qslot], 1);
        __syncthreads();
        const int tile = s_tile;
        __syncthreads();
        if (tile >= ntiles) break;

        const int row0 = tile * 64;
        const int grA  = row0 + arA;
        const bool rokA = (grA < M);

        float acc[2][4][4];
#pragma unroll
        for (int mt = 0; mt < 2; mt++)
#pragma unroll
            for (int nt = 0; nt < 4; nt++)
#pragma unroll
                for (int j = 0; j < 4; j++) acc[mt][nt][j] = 0.f;

        float4 va;
        uint4 pa;
        uint32_t wk[4];

        auto prefetch = [&](int t) {
            if (PACKED) {
                int gp = t * 4 + kgA;
                pa = make_uint4(0u, 0u, 0u, 0u);
                if (rokA && gp < KP4) pa = Apk[(size_t)grA * KP4 + gp];
            } else {
                int gk0 = t * 16 + 4 * kgA;
                va = make_float4(0.f, 0.f, 0.f, 0.f);
                if (rokA && gk0 < K) va = *(const float4*)&A[(size_t)grA * K + gk0];
            }
#pragma unroll
            for (int j = 0; j < 4; j++) {
                int kp = t * 8 + kgW + 2 * j;
                wk[j] = (kp < KP) ? wpk[kp * DHF + arW] : 0u;
            }
        };

        auto stage = [&](int d, int k0) {
            if (PACKED) {
                ash[d][2 * kgA][arA]     = pa.x;
                ash[d][2 * kgA + 1][arA] = pa.y;
                asl[d][2 * kgA][arA]     = pa.z;
                asl[d][2 * kgA + 1][arA] = pa.w;
            } else {
                float a4[4] = {va.x, va.y, va.z, va.w};
                if (bnga && rokA) {
#pragma unroll
                    for (int j = 0; j < 4; j++) {
                        int gk = k0 + 4 * kgA + j;
                        a4[j] = (gk < K) ? fmaxf(a4[j] * strs[gk] + strh[gk], 0.f) : 0.f;
                    }
                }
#pragma unroll
                for (int p = 0; p < 2; p++) {
                    float r0f, r1f;
                    ash[d][2 * kgA + p][arA] = pack_f16(a4[2 * p], a4[2 * p + 1], r0f, r1f);
                    asl[d][2 * kgA + p][arA] = pack_f16_rn(r0f, r1f);
                }
            }
#pragma unroll
            for (int j = 0; j < 4; j++)
                wsh[d][kgW + 2 * j][arW] = wk[j];
        };

        prefetch(0);
        stage(0, 0);
        __syncthreads();

        for (int t = 0; t < T; t++) {
            const int cur = t & 1;
            if (t + 1 < T) prefetch(t + 1);

            {
                uint32_t bh[4][2];
#pragma unroll
                for (int nt = 0; nt < 4; nt++) {
                    int col = wc * 32 + nt * 8 + gid;
                    bh[nt][0] = wsh[cur][tq][col];
                    bh[nt][1] = wsh[cur][tq + 4][col];
                }
#pragma unroll
                for (int mt = 0; mt < 2; mt++) {
                    int r0 = wr * 32 + mt * 16;
                    uint32_t ah[4], al[4];
                    ah[0] = ash[cur][tq][r0 + gid];
                    ah[1] = ash[cur][tq][r0 + gid + 8];
                    ah[2] = ash[cur][tq + 4][r0 + gid];
                    ah[3] = ash[cur][tq + 4][r0 + gid + 8];
                    al[0] = asl[cur][tq][r0 + gid];
                    al[1] = asl[cur][tq][r0 + gid + 8];
                    al[2] = asl[cur][tq + 4][r0 + gid];
                    al[3] = asl[cur][tq + 4][r0 + gid + 8];
#pragma unroll
                    for (int nt = 0; nt < 4; nt++) {
                        mma16(acc[mt][nt], ah, bh[nt]);   // hiA * W
                        mma16(acc[mt][nt], al, bh[nt]);   // loA * W
                    }
                }
            }

            if (t + 1 < T) stage((t + 1) & 1, (t + 1) * 16);
            __syncthreads();
        }

        // ---- epilogue: bias, store, column stats ----
        float cs[4][2], cq[4][2];
#pragma unroll
        for (int nt = 0; nt < 4; nt++)
#pragma unroll
            for (int j = 0; j < 2; j++) { cs[nt][j] = 0.f; cq[nt][j] = 0.f; }

#pragma unroll
        for (int mt = 0; mt < 2; mt++) {
            int rbase = row0 + wr * 32 + mt * 16;
#pragma unroll
            for (int nt = 0; nt < 4; nt++) {
                int colb = wc * 32 + nt * 8 + 2 * tq;
                float b0 = bias[colb], b1 = bias[colb + 1];
                int r1 = rbase + gid;
                int r2 = rbase + gid + 8;
                if (r1 < M) {
                    float v0 = acc[mt][nt][0] + b0;
                    float v1 = acc[mt][nt][1] + b1;
                    *(float2*)&C[(size_t)r1 * 128 + colb] = make_float2(v0, v1);
                    cs[nt][0] += v0; cq[nt][0] += v0 * v0;
                    cs[nt][1] += v1; cq[nt][1] += v1 * v1;
                }
                if (r2 < M) {
                    float v0 = acc[mt][nt][2] + b0;
                    float v1 = acc[mt][nt][3] + b1;
                    *(float2*)&C[(size_t)r2 * 128 + colb] = make_float2(v0, v1);
                    cs[nt][0] += v0; cq[nt][0] += v0 * v0;
                    cs[nt][1] += v1; cq[nt][1] += v1 * v1;
                }
            }
        }
#pragma unroll
        for (int nt = 0; nt < 4; nt++)
#pragma unroll
            for (int j = 0; j < 2; j++) {
                float s = cs[nt][j], q = cq[nt][j];
                s += __shfl_xor_sync(0xffffffffu, s, 4);
                s += __shfl_xor_sync(0xffffffffu, s, 8);
                s += __shfl_xor_sync(0xffffffffu, s, 16);
                q += __shfl_xor_sync(0xffffffffu, q, 4);
                q += __shfl_xor_sync(0xffffffffu, q, 8);
                q += __shfl_xor_sync(0xffffffffu, q, 16);
                if (gid == 0) {
                    int col = wc * 32 + nt * 8 + 2 * tq + j;
                    atomicAdd(&osum[col], s);
                    atomicAdd(&osumsq[col], q);
                }
            }
        __syncthreads();
    }
}

// ------ fused BN + ReLU + graph pool: register-batched, 32 rows/block ------
__global__ void k_bnpool(const float* __restrict__ rep, float* __restrict__ h,
                         float* __restrict__ out, int off,
                         const float* __restrict__ gamma, const float* __restrict__ beta,
                         const int* __restrict__ gids, int slot, int write_h) {
    int c = threadIdx.x;
    int r0 = blockIdx.x * BNP_ROWS;
    int nr = min(BNP_ROWS, NN - r0);
    const float invN = 1.0f / NN;
    float m = g_sum[slot][c] * invN;
    float v = g_sumsq[slot][c] * invN - m * m;
    float sc = gamma[c] * rsqrtf(v + BN_EPS);
    float sh = beta[c] - m * sc;

    float vals[BNP_ROWS];
    int gv[BNP_ROWS];
    if (nr == BNP_ROWS) {
#pragma unroll
        for (int i = 0; i < BNP_ROWS; i++) {
            vals[i] = rep[(size_t)(r0 + i) * DHF + c];
            gv[i] = gids[r0 + i];
        }
#pragma unroll
        for (int i = 0; i < BNP_ROWS; i++)
            vals[i] = fmaxf(vals[i] * sc + sh, 0.f);
        if (write_h) {
#pragma unroll
            for (int i = 0; i < BNP_ROWS; i++)
                h[(size_t)(r0 + i) * DHF + c] = vals[i];
        }
    } else {
        for (int i = 0; i < nr; i++) {
            vals[i] = rep[(size_t)(r0 + i) * DHF + c];
            gv[i] = gids[r0 + i];
        }
        for (int i = 0; i < nr; i++) {
            vals[i] = fmaxf(vals[i] * sc + sh, 0.f);
            if (write_h) h[(size_t)(r0 + i) * DHF + c] = vals[i];
        }
    }

    int curg = gv[0];
    float acc = 0.f;
    for (int i = 0; i < nr; i++) {
        if (gv[i] != curg) {
            atomicAdd(&out[(size_t)curg * OUTW + off + c], acc);
            acc = 0.f;
            curg = gv[i];
        }
        acc += vals[i];
    }
    atomicAdd(&out[(size_t)curg * OUTW + off + c], acc);
}

__global__ void k_poolx(const float* __restrict__ src, float* __restrict__ out,
                        const int* __restrict__ gids) {
    int c = threadIdx.x;
    if (c >= DINF) return;
    int r0 = blockIdx.x * BNP_ROWS;
    int nr = min(BNP_ROWS, NN - r0);

    float vals[BNP_ROWS];
    int gv[BNP_ROWS];
    if (nr == BNP_ROWS) {
#pragma unroll
        for (int i = 0; i < BNP_ROWS; i++) {
            vals[i] = src[(size_t)(r0 + i) * DINF + c];
            gv[i] = gids[r0 + i];
        }
    } else {
        for (int i = 0; i < nr; i++) {
            vals[i] = src[(size_t)(r0 + i) * DINF + c];
            gv[i] = gids[r0 + i];
        }
    }

    int curg = gv[0];
    float acc = 0.f;
    for (int i = 0; i < nr; i++) {
        if (gv[i] != curg) {
            atomicAdd(&out[(size_t)curg * OUTW + c], acc);
            acc = 0.f;
            curg = gv[i];
        }
        acc += vals[i];
    }
    atomicAdd(&out[(size_t)curg * OUTW + c], acc);
}

// ---------------- launch ---------------------------------------------------
extern "C" void kernel_launch(void* const* d_in, const int* in_sizes, int n_in,
                              void* d_out, int out_size) {
    const float* x     = (const float*)d_in[0];
    const int*   erow  = (const int*)d_in[1];
    const int*   ecol  = (const int*)d_in[2];
    const int*   gid   = (const int*)d_in[3];
    const float* eps   = (const float*)d_in[4];
    const float* w1_0  = (const float*)d_in[5];
    const float* b1_0  = (const float*)d_in[6];
    const float* g1_0  = (const float*)d_in[7];
    const float* be1_0 = (const float*)d_in[8];
    const float* w2_0  = (const float*)d_in[9];
    const float* b2_0  = (const float*)d_in[10];
    const float* gbn_0 = (const float*)d_in[11];
    const float* bbn_0 = (const float*)d_in[12];
    const float* w1_r  = (const float*)d_in[13];
    const float* b1_r  = (const float*)d_in[14];
    const float* g1_r  = (const float*)d_in[15];
    const float* be1_r = (const float*)d_in[16];
    const float* w2_r  = (const float*)d_in[17];
    const float* b2_r  = (const float*)d_in[18];
    const float* gbn_r = (const float*)d_in[19];
    const float* bbn_r = (const float*)d_in[20];
    float* out = (float*)d_out;

    int E = in_sizes[1];

    float *mid, *rep, *h, *sumb, *sumsqb;
    uint4 *apk;
    uint32_t *wpk;
    cudaGetSymbolAddress((void**)&apk,    g_apk);
    cudaGetSymbolAddress((void**)&mid,    g_mid);
    cudaGetSymbolAddress((void**)&rep,    g_rep);
    cudaGetSymbolAddress((void**)&h,      g_h);
    cudaGetSymbolAddress((void**)&sumb,   g_sum);
    cudaGetSymbolAddress((void**)&sumsqb, g_sumsq);
    cudaGetSymbolAddress((void**)&wpk,    g_wpk);

    const int scan_smem = (NN + 1024) * (int)sizeof(int);
    cudaFuncSetAttribute(k_scan_big, cudaFuncAttributeMaxDynamicSharedMemorySize, scan_smem);
    cudaFuncSetAttribute(k_gemm_tc<0>, cudaFuncAttributeMaxDynamicSharedMemorySize, GEMM_SMEM_PAD);
    cudaFuncSetAttribute(k_gemm_tc<1>, cudaFuncAttributeMaxDynamicSharedMemorySize, GEMM_SMEM_PAD);

    k_packw<<<WPAIRS, DHF>>>(w1_0, w2_0, w1_r, w2_r, out, out_size);
    k_hist<<<(E + 255) / 256, 256>>>(erow, E);
    k_scan_big<<<1, 1024, scan_smem>>>();              // + zero cursors/stats/qctr
    k_scatter<<<(E + 255) / 256, 256>>>(erow, ecol, E);

    const int spmm_blocks = (NN + 7) / 8;
    const int ntiles = (NN + 63) / 64;
    const int pool_blocks = (NN + BNP_ROWS - 1) / BNP_ROWS;

    const int woff_g1[NLAY] = {0, 164, 228, 292};
    const int woff_g2[NLAY] = {100, 356, 420, 484};

    for (int l = 0; l < NLAY; l++) {
        const float *ba, *ga, *bea, *bb, *gb, *bbb;
        int K1;
        if (l == 0) {
            k_spmm<DINF / 4><<<spmm_blocks, 256>>>(x, apk, eps, 0);
            K1 = DINF;
            ba = b1_0; ga = g1_0; bea = be1_0;
            bb = b2_0; gb = gbn_0; bbb = bbn_0;
        } else {
            k_spmm<DHF / 4><<<spmm_blocks, 256>>>(h, apk, eps, l);
            K1 = DHF;
            int o1 = (l - 1) * DHF;
            ba = b1_r + o1; ga = g1_r + o1; bea = be1_r + o1;
            bb = b2_r + o1; gb = gbn_r + o1; bbb = bbn_r + o1;
        }

        k_gemm_tc<1><<<GEMM_GRID, 256, GEMM_SMEM_PAD>>>(
            nullptr, apk, wpk + woff_g1[l] * DHF, ba, mid, NN, K1, ntiles, 2 * l,
            nullptr, nullptr, nullptr, nullptr,
            sumb + (2 * l) * DHF, sumsqb + (2 * l) * DHF);
        k_gemm_tc<0><<<GEMM_GRID, 256, GEMM_SMEM_PAD>>>(
            mid, nullptr, wpk + woff_g2[l] * DHF, bb, rep, NN, DHF, ntiles, 2 * l + 1,
            ga, bea, sumb + (2 * l) * DHF, sumsqb + (2 * l) * DHF,
            sumb + (2 * l + 1) * DHF, sumsqb + (2 * l + 1) * DHF);

        k_bnpool<<<pool_blocks, DHF>>>(rep, h, out, DINF + l * DHF, gb, bbb,
                                       gid, 2 * l + 1, (l < NLAY - 1) ? 1 : 0);
    }

    k_poolx<<<pool_blocks, 256>>>(x, out, gid);
}

// round 13
// speedup vs baseline: 1.2973x; 1.0425x over previous
#include <cuda_runtime.h>
#include <cuda_fp16.h>
#include <cstdint>

// Problem constants (fixed-shape problem)
#define NN      50000
#define EE_MAX  800000
#define GG      128
#define DINF    200
#define DHF     128
#define NLAY    4
#define BN_EPS  1e-5f
#define OUTW    (DINF + NLAY * DHF)   // 712
#define WPAIRS  548
#define APK_W   50
#define NTILES  ((NN + 63) / 64)      // 782
#define BNP_CH  16                    // rows per bnpool chunk

// ---------------- scratch (device globals; no allocation allowed) ----------
__device__ uint4    g_apk    [NN * APK_W];
__device__ float    g_mid    [NN * DHF];
__device__ float    g_rep    [NN * DHF];
__device__ float    g_h      [NN * DHF];
__device__ int      g_cnt    [2 * NN];
__device__ int      g_rowptr [NN + 1];
__device__ int      g_colidx [EE_MAX];
__device__ float    g_sum    [2 * NLAY][DHF];
__device__ float    g_sumsq  [2 * NLAY][DHF];
__device__ uint32_t g_wpk    [WPAIRS * DHF];       // fp16x2 of W pair-rows
__device__ unsigned g_bar_cnt;
__device__ unsigned g_bar_gen;

// ---------------- device-wide barrier (all blocks resident) ----------------
__device__ __forceinline__ void grid_sync() {
    __syncthreads();
    if (threadIdx.x == 0) {
        unsigned gen = *(volatile unsigned*)&g_bar_gen;
        __threadfence();
        unsigned ticket = atomicAdd(&g_bar_cnt, 1u);
        if (ticket == gridDim.x - 1) {
            g_bar_cnt = 0u;
            __threadfence();
            atomicAdd(&g_bar_gen, 1u);
        } else {
            while (*(volatile unsigned*)&g_bar_gen == gen) __nanosleep(64);
        }
        __threadfence();
    }
    __syncthreads();
}

// ---------------- fp16 hi/lo split helpers ---------------------------------
__device__ __forceinline__ uint32_t pack_f16(float v0, float v1, float& rem0, float& rem1) {
    __half h0 = __float2half_rn(v0);
    __half h1 = __float2half_rn(v1);
    rem0 = v0 - __half2float(h0);
    rem1 = v1 - __half2float(h1);
    return ((uint32_t)__half_as_ushort(h1) << 16) | (uint32_t)__half_as_ushort(h0);
}
__device__ __forceinline__ uint32_t pack_f16_rn(float v0, float v1) {
    __half2 p = __floats2half2_rn(v0, v1);   // .x = v0 (low half)
    return *(uint32_t*)&p;
}

// -------- weight prepack (fp16) + hist zero + out zero ---------------------
__global__ void k_packw(const float* __restrict__ w1_0, const float* __restrict__ w2_0,
                        const float* __restrict__ w1_r, const float* __restrict__ w2_r,
                        float* __restrict__ out, int out_n) {
    int b = blockIdx.x;
    int c = threadIdx.x;
    int gtid = b * DHF + c;
    for (int i = gtid; i < NN; i += WPAIRS * DHF) g_cnt[i] = 0;
    for (int i = gtid; i < out_n; i += WPAIRS * DHF) out[i] = 0.f;

    const float* src;
    int kp;
    if (b < 100)      { src = w1_0; kp = b; }
    else if (b < 164) { src = w2_0; kp = b - 100; }
    else {
        int r = b - 164;
        if (r < 192) { src = w1_r + (r / 64) * DHF * DHF; kp = r % 64; }
        else { r -= 192; src = w2_r + (r / 64) * DHF * DHF; kp = r % 64; }
    }
    float v0 = src[(size_t)(2 * kp) * DHF + c];
    float v1 = src[(size_t)(2 * kp + 1) * DHF + c];
    g_wpk[b * DHF + c] = pack_f16_rn(v0, v1);
}

// ---------------- CSR build ------------------------------------------------
__global__ void k_hist(const int* __restrict__ erow, int E) {
    int e = blockIdx.x * blockDim.x + threadIdx.x;
    if (e < E) atomicAdd(&g_cnt[erow[e]], 1);
}

__global__ void k_scan_big() {
    extern __shared__ int sc[];
    int* part = sc + NN;
    const int T = 1024;
    int t = threadIdx.x;

    if (t < DHF) {
        for (int l = 0; l < 2 * NLAY; l++) { g_sum[l][t] = 0.f; g_sumsq[l][t] = 0.f; }
    }
    for (int i = t; i < NN; i += T) {
        sc[i] = g_cnt[i];
        g_cnt[NN + i] = 0;
    }
    __syncthreads();

    const int C = (NN + T - 1) / T;
    int base = t * C;
    int s = 0;
    for (int j = 0; j < C; j++) {
        int i = base + j;
        if (i < NN) s += sc[i];
    }
    part[t] = s;
    __syncthreads();
    for (int off = 1; off < T; off <<= 1) {
        int v = (t >= off) ? part[t - off] : 0;
        __syncthreads();
        part[t] += v;
        __syncthreads();
    }
    int pre = (t > 0) ? part[t - 1] : 0;
    for (int j = 0; j < C; j++) {
        int i = base + j;
        if (i < NN) {
            int c = sc[i];
            sc[i] = pre;
            pre += c;
        }
    }
    __syncthreads();
    for (int i = t; i < NN; i += T) g_rowptr[i] = sc[i];
    if (t == T - 1) g_rowptr[NN] = pre;
}

__global__ void k_scatter(const int* __restrict__ erow, const int* __restrict__ ecol, int E) {
    int e = blockIdx.x * blockDim.x + threadIdx.x;
    if (e < E) {
        int r = erow[e];
        int p = g_rowptr[r] + atomicAdd(&g_cnt[NN + r], 1);
        g_colidx[p] = ecol[e];
    }
}

// ---------------- fused layer kernel phases ---------------------------------
__device__ __forceinline__ void mma16(float* c, const uint32_t* a, const uint32_t* b) {
    asm volatile(
        "mma.sync.aligned.m16n8k16.row.col.f32.f16.f16.f32 "
        "{%0,%1,%2,%3}, {%4,%5,%6,%7}, {%8,%9}, {%0,%1,%2,%3};"
        : "+f"(c[0]), "+f"(c[1]), "+f"(c[2]), "+f"(c[3])
        : "r"(a[0]), "r"(a[1]), "r"(a[2]), "r"(a[3]), "r"(b[0]), "r"(b[1]));
}

struct GemmSmem {
    uint32_t ash[2][8][72], asl[2][8][72];
    uint32_t wsh[2][8][136];
    float strs[DHF], strh[DHF];
};

// phase A: spmm (warp per node, strided) emitting packed hi/lo fp16 A
template <int D4>
__device__ void spmm_phase(const float* __restrict__ hin, uint4* __restrict__ pout,
                           float se) {
    const int S = (D4 + 31) / 32;
    int lane = threadIdx.x & 31;
    int wstride = gridDim.x * 8;
    for (int wid = blockIdx.x * 8 + (threadIdx.x >> 5); wid < NN; wid += wstride) {
        const float4* selfr = (const float4*)hin + (size_t)wid * D4;
        float4 acc[S];
#pragma unroll
        for (int s = 0; s < S; s++) {
            int j = lane + 32 * s;
            if (j < D4) {
                float4 v = selfr[j];
                acc[s] = make_float4(v.x * se, v.y * se, v.z * se, v.w * se);
            } else acc[s] = make_float4(0.f, 0.f, 0.f, 0.f);
        }
        int e0 = g_rowptr[wid], e1 = g_rowptr[wid + 1];
        int e = e0;
        for (; e + 4 <= e1; e += 4) {
            int c0 = g_colidx[e], c1 = g_colidx[e + 1];
            int c2 = g_colidx[e + 2], c3 = g_colidx[e + 3];
            const float4* r0 = (const float4*)hin + (size_t)c0 * D4;
            const float4* r1 = (const float4*)hin + (size_t)c1 * D4;
            const float4* r2 = (const float4*)hin + (size_t)c2 * D4;
            const float4* r3 = (const float4*)hin + (size_t)c3 * D4;
#pragma unroll
            for (int s = 0; s < S; s++) {
                int j = lane + 32 * s;
                if (j < D4) {
                    float4 v0 = r0[j], v1 = r1[j], v2 = r2[j], v3 = r3[j];
                    acc[s].x += (v0.x + v1.x) + (v2.x + v3.x);
                    acc[s].y += (v0.y + v1.y) + (v2.y + v3.y);
                    acc[s].z += (v0.z + v1.z) + (v2.z + v3.z);
                    acc[s].w += (v0.w + v1.w) + (v2.w + v3.w);
                }
            }
        }
        for (; e < e1; e++) {
            int c = g_colidx[e];
            const float4* r = (const float4*)hin + (size_t)c * D4;
#pragma unroll
            for (int s = 0; s < S; s++) {
                int j = lane + 32 * s;
                if (j < D4) {
                    float4 v = r[j];
                    acc[s].x += v.x; acc[s].y += v.y; acc[s].z += v.z; acc[s].w += v.w;
                }
            }
        }
        uint4* o = pout + (size_t)wid * D4;
#pragma unroll
        for (int s = 0; s < S; s++) {
            int j = lane + 32 * s;
            if (j < D4) {
                float r0, r1, r2, r3;
                uint32_t h01 = pack_f16(acc[s].x, acc[s].y, r0, r1);
                uint32_t h23 = pack_f16(acc[s].z, acc[s].w, r2, r3);
                o[j] = make_uint4(h01, h23, pack_f16_rn(r0, r1), pack_f16_rn(r2, r3));
            }
        }
    }
}

// GEMM phase: 64-row tiles strided by block; 2-term fp16 split.
// PACKED=1: A pre-packed (uint4 per 4k). PACKED=0: fp32 A + in-phase BN+ReLU.
template <int PACKED>
__device__ void gemm_phase(GemmSmem& sm,
                           const float* __restrict__ A, const uint4* __restrict__ Apk,
                           const uint32_t* __restrict__ wpk,
                           const float* __restrict__ bias, float* __restrict__ C, int K,
                           const float* __restrict__ bnga, const float* __restrict__ bnbe,
                           const float* __restrict__ psum, const float* __restrict__ psq,
                           float* __restrict__ osum, float* __restrict__ osumsq) {
    const int tid  = threadIdx.x;
    const int lane = tid & 31;
    const int wid  = tid >> 5;
    const int wr   = wid >> 2;
    const int wc   = wid & 3;
    const int gid  = lane >> 2;
    const int tq   = lane & 3;
    const int arA = tid & 63;
    const int kgA = tid >> 6;
    const int arW = tid & 127;
    const int kgW = tid >> 7;
    const int KP  = K >> 1;
    const int KP4 = K >> 2;
    const int T   = (K + 15) >> 4;

    if (!PACKED) {
        if (tid < DHF) {
            const float invN = 1.0f / NN;
            float m = psum[tid] * invN;
            float v = psq[tid] * invN - m * m;
            float sc = bnga[tid] * rsqrtf(v + BN_EPS);
            sm.strs[tid] = sc;
            sm.strh[tid] = bnbe[tid] - m * sc;
        }
        __syncthreads();
    }

    for (int tile = blockIdx.x; tile < NTILES; tile += gridDim.x) {
        const int row0 = tile * 64;
        const int grA  = row0 + arA;
        const bool rokA = (grA < NN);

        float acc[2][4][4];
#pragma unroll
        for (int mt = 0; mt < 2; mt++)
#pragma unroll
            for (int nt = 0; nt < 4; nt++)
#pragma unroll
                for (int j = 0; j < 4; j++) acc[mt][nt][j] = 0.f;

        float4 va;
        uint4 pa;
        uint32_t wk[4];

        auto prefetch = [&](int t) {
            if (PACKED) {
                int gp = t * 4 + kgA;
                pa = make_uint4(0u, 0u, 0u, 0u);
                if (rokA && gp < KP4) pa = Apk[(size_t)grA * KP4 + gp];
            } else {
                int gk0 = t * 16 + 4 * kgA;
                va = make_float4(0.f, 0.f, 0.f, 0.f);
                if (rokA && gk0 < K) va = *(const float4*)&A[(size_t)grA * K + gk0];
            }
#pragma unroll
            for (int j = 0; j < 4; j++) {
                int kp = t * 8 + kgW + 2 * j;
                wk[j] = (kp < KP) ? wpk[kp * DHF + arW] : 0u;
            }
        };

        auto stage = [&](int d, int k0) {
            if (PACKED) {
                sm.ash[d][2 * kgA][arA]     = pa.x;
                sm.ash[d][2 * kgA + 1][arA] = pa.y;
                sm.asl[d][2 * kgA][arA]     = pa.z;
                sm.asl[d][2 * kgA + 1][arA] = pa.w;
            } else {
                float a4[4] = {va.x, va.y, va.z, va.w};
                if (rokA) {
#pragma unroll
                    for (int j = 0; j < 4; j++) {
                        int gk = k0 + 4 * kgA + j;
                        a4[j] = (gk < K) ? fmaxf(a4[j] * sm.strs[gk] + sm.strh[gk], 0.f) : 0.f;
                    }
                }
#pragma unroll
                for (int p = 0; p < 2; p++) {
                    float r0f, r1f;
                    sm.ash[d][2 * kgA + p][arA] = pack_f16(a4[2 * p], a4[2 * p + 1], r0f, r1f);
                    sm.asl[d][2 * kgA + p][arA] = pack_f16_rn(r0f, r1f);
                }
            }
#pragma unroll
            for (int j = 0; j < 4; j++)
                sm.wsh[d][kgW + 2 * j][arW] = wk[j];
        };

        prefetch(0);
        stage(0, 0);
        __syncthreads();

        for (int t = 0; t < T; t++) {
            const int cur = t & 1;
            if (t + 1 < T) prefetch(t + 1);
            {
                uint32_t bh[4][2];
#pragma unroll
                for (int nt = 0; nt < 4; nt++) {
                    int col = wc * 32 + nt * 8 + gid;
                    bh[nt][0] = sm.wsh[cur][tq][col];
                    bh[nt][1] = sm.wsh[cur][tq + 4][col];
                }
#pragma unroll
                for (int mt = 0; mt < 2; mt++) {
                    int r0 = wr * 32 + mt * 16;
                    uint32_t ah[4], al[4];
                    ah[0] = sm.ash[cur][tq][r0 + gid];
                    ah[1] = sm.ash[cur][tq][r0 + gid + 8];
                    ah[2] = sm.ash[cur][tq + 4][r0 + gid];
                    ah[3] = sm.ash[cur][tq + 4][r0 + gid + 8];
                    al[0] = sm.asl[cur][tq][r0 + gid];
                    al[1] = sm.asl[cur][tq][r0 + gid + 8];
                    al[2] = sm.asl[cur][tq + 4][r0 + gid];
                    al[3] = sm.asl[cur][tq + 4][r0 + gid + 8];
#pragma unroll
                    for (int nt = 0; nt < 4; nt++) {
                        mma16(acc[mt][nt], ah, bh[nt]);   // hiA * W
                        mma16(acc[mt][nt], al, bh[nt]);   // loA * W
                    }
                }
            }
            if (t + 1 < T) stage((t + 1) & 1, (t + 1) * 16);
            __syncthreads();
        }

        // epilogue: bias, store, column stats
        float cs[4][2], cq[4][2];
#pragma unroll
        for (int nt = 0; nt < 4; nt++)
#pragma unroll
            for (int j = 0; j < 2; j++) { cs[nt][j] = 0.f; cq[nt][j] = 0.f; }

#pragma unroll
        for (int mt = 0; mt < 2; mt++) {
            int rbase = row0 + wr * 32 + mt * 16;
#pragma unroll
            for (int nt = 0; nt < 4; nt++) {
                int colb = wc * 32 + nt * 8 + 2 * tq;
                float b0 = bias[colb], b1 = bias[colb + 1];
                int r1 = rbase + gid;
                int r2 = rbase + gid + 8;
                if (r1 < NN) {
                    float v0 = acc[mt][nt][0] + b0;
                    float v1 = acc[mt][nt][1] + b1;
                    *(float2*)&C[(size_t)r1 * 128 + colb] = make_float2(v0, v1);
                    cs[nt][0] += v0; cq[nt][0] += v0 * v0;
                    cs[nt][1] += v1; cq[nt][1] += v1 * v1;
                }
                if (r2 < NN) {
                    float v0 = acc[mt][nt][2] + b0;
                    float v1 = acc[mt][nt][3] + b1;
                    *(float2*)&C[(size_t)r2 * 128 + colb] = make_float2(v0, v1);
                    cs[nt][0] += v0; cq[nt][0] += v0 * v0;
                    cs[nt][1] += v1; cq[nt][1] += v1 * v1;
                }
            }
        }
#pragma unroll
        for (int nt = 0; nt < 4; nt++)
#pragma unroll
            for (int j = 0; j < 2; j++) {
                float s = cs[nt][j], q = cq[nt][j];
                s += __shfl_xor_sync(0xffffffffu, s, 4);
                s += __shfl_xor_sync(0xffffffffu, s, 8);
                s += __shfl_xor_sync(0xffffffffu, s, 16);
                q += __shfl_xor_sync(0xffffffffu, q, 4);
                q += __shfl_xor_sync(0xffffffffu, q, 8);
                q += __shfl_xor_sync(0xffffffffu, q, 16);
                if (gid == 0) {
                    int col = wc * 32 + nt * 8 + 2 * tq + j;
                    atomicAdd(&osum[col], s);
                    atomicAdd(&osumsq[col], q);
                }
            }
        __syncthreads();
    }
}

// phase D: BN+ReLU+pool, 16-row chunks, two chunks per block pass
__device__ void bnpool_phase(const float* __restrict__ rep, float* __restrict__ h,
                             float* __restrict__ out, int off,
                             const float* __restrict__ gamma, const float* __restrict__ beta,
                             const int* __restrict__ gids, int slot, int write_h) {
    int c = threadIdx.x & 127;
    int half = threadIdx.x >> 7;
    const float invN = 1.0f / NN;
    float m = g_sum[slot][c] * invN;
    float v = g_sumsq[slot][c] * invN - m * m;
    float sc = gamma[c] * rsqrtf(v + BN_EPS);
    float sh = beta[c] - m * sc;

    const int nch = NN / BNP_CH;   // 3125 exact
    for (int cc = blockIdx.x * 2 + half; cc < nch; cc += gridDim.x * 2) {
        int r0 = cc * BNP_CH;
        float vals[BNP_CH];
        int gv[BNP_CH];
#pragma unroll
        for (int i = 0; i < BNP_CH; i++) {
            vals[i] = rep[(size_t)(r0 + i) * DHF + c];
            gv[i] = gids[r0 + i];
        }
#pragma unroll
        for (int i = 0; i < BNP_CH; i++)
            vals[i] = fmaxf(vals[i] * sc + sh, 0.f);
        if (write_h) {
#pragma unroll
            for (int i = 0; i < BNP_CH; i++)
                h[(size_t)(r0 + i) * DHF + c] = vals[i];
        }
        int curg = gv[0];
        float acc = 0.f;
#pragma unroll
        for (int i = 0; i < BNP_CH; i++) {
            if (gv[i] != curg) {
                atomicAdd(&out[(size_t)curg * OUTW + off + c], acc);
                acc = 0.f;
                curg = gv[i];
            }
            acc += vals[i];
        }
        atomicAdd(&out[(size_t)curg * OUTW + off + c], acc);
    }
}

// raw-x pooling (layer 0 only), 16-row chunks strided
__device__ void poolx_phase(const float* __restrict__ src, float* __restrict__ out,
                            const int* __restrict__ gids) {
    int c = threadIdx.x;
    if (c >= DINF) return;
    const int nch = NN / BNP_CH;
    for (int cc = blockIdx.x; cc < nch; cc += gridDim.x) {
        int r0 = cc * BNP_CH;
        float vals[BNP_CH];
        int gv[BNP_CH];
#pragma unroll
        for (int i = 0; i < BNP_CH; i++) {
            vals[i] = src[(size_t)(r0 + i) * DINF + c];
            gv[i] = gids[r0 + i];
        }
        int curg = gv[0];
        float acc = 0.f;
#pragma unroll
        for (int i = 0; i < BNP_CH; i++) {
            if (gv[i] != curg) {
                atomicAdd(&out[(size_t)curg * OUTW + c], acc);
                acc = 0.f;
                curg = gv[i];
            }
            acc += vals[i];
        }
        atomicAdd(&out[(size_t)curg * OUTW + c], acc);
    }
}

// ---------------- fused layer kernel ----------------------------------------
__global__ __launch_bounds__(256, 3)
void k_layer(const float* __restrict__ hin, const float* __restrict__ epsv, int li, int K1,
             const uint32_t* __restrict__ wpk1, const float* __restrict__ b1,
             const uint32_t* __restrict__ wpk2, const float* __restrict__ b2,
             const float* __restrict__ ga, const float* __restrict__ bea,
             const float* __restrict__ gb, const float* __restrict__ bbb,
             const int* __restrict__ gids, float* __restrict__ out,
             int off, int write_h, int do_poolx) {
    __shared__ GemmSmem gsm;

    // phase A: spmm (+ poolx on layer 0)
    {
        float se = 1.0f + epsv[li];
        if (li == 0) spmm_phase<DINF / 4>(hin, g_apk, se);
        else         spmm_phase<DHF / 4>(hin, g_apk, se);
        if (do_poolx) poolx_phase(hin, out, gids);
    }
    grid_sync();

    // phase B: GEMM1 (packed A) -> mid + stats[2l]
    gemm_phase<1>(gsm, nullptr, g_apk, wpk1, b1, g_mid, K1,
                  nullptr, nullptr, nullptr, nullptr,
                  g_sum[2 * li], g_sumsq[2 * li]);
    grid_sync();

    // phase C: BN-fold + GEMM2 (fp32 A=mid) -> rep + stats[2l+1]
    gemm_phase<0>(gsm, g_mid, nullptr, wpk2, b2, g_rep, DHF,
                  ga, bea, g_sum[2 * li], g_sumsq[2 * li],
                  g_sum[2 * li + 1], g_sumsq[2 * li + 1]);
    grid_sync();

    // phase D: BN + ReLU + pool (+ write h for layers 0..2)
    bnpool_phase(g_rep, g_h, out, off, gb, bbb, gids, 2 * li + 1, write_h);
}

// ---------------- launch ---------------------------------------------------
extern "C" void kernel_launch(void* const* d_in, const int* in_sizes, int n_in,
                              void* d_out, int out_size) {
    const float* x     = (const float*)d_in[0];
    const int*   erow  = (const int*)d_in[1];
    const int*   ecol  = (const int*)d_in[2];
    const int*   gid   = (const int*)d_in[3];
    const float* eps   = (const float*)d_in[4];
    const float* w1_0  = (const float*)d_in[5];
    const float* b1_0  = (const float*)d_in[6];
    const float* g1_0  = (const float*)d_in[7];
    const float* be1_0 = (const float*)d_in[8];
    const float* w2_0  = (const float*)d_in[9];
    const float* b2_0  = (const float*)d_in[10];
    const float* gbn_0 = (const float*)d_in[11];
    const float* bbn_0 = (const float*)d_in[12];
    const float* w1_r  = (const float*)d_in[13];
    const float* b1_r  = (const float*)d_in[14];
    const float* g1_r  = (const float*)d_in[15];
    const float* be1_r = (const float*)d_in[16];
    const float* w2_r  = (const float*)d_in[17];
    const float* b2_r  = (const float*)d_in[18];
    const float* gbn_r = (const float*)d_in[19];
    const float* bbn_r = (const float*)d_in[20];
    float* out = (float*)d_out;

    int E = in_sizes[1];

    float *hbuf;
    uint32_t *wpk;
    cudaGetSymbolAddress((void**)&hbuf, g_h);
    cudaGetSymbolAddress((void**)&wpk,  g_wpk);

    const int scan_smem = (NN + 1024) * (int)sizeof(int);
    cudaFuncSetAttribute(k_scan_big, cudaFuncAttributeMaxDynamicSharedMemorySize, scan_smem);

    // resident-grid size: SMs x achievable occupancy (guarantees barrier safety)
    int dev = 0;
    cudaGetDevice(&dev);
    int nsm = 0;
    cudaDeviceGetAttribute(&nsm, cudaDevAttrMultiProcessorCount, dev);
    int occ = 0;
    cudaOccupancyMaxActiveBlocksPerMultiprocessor(&occ, k_layer, 256, 0);
    if (occ < 1) occ = 1;
    const int lgrid = nsm * occ;

    k_packw<<<WPAIRS, DHF>>>(w1_0, w2_0, w1_r, w2_r, out, out_size);
    k_hist<<<(E + 255) / 256, 256>>>(erow, E);
    k_scan_big<<<1, 1024, scan_smem>>>();
    k_scatter<<<(E + 255) / 256, 256>>>(erow, ecol, E);

    const int woff_g1[NLAY] = {0, 164, 228, 292};
    const int woff_g2[NLAY] = {100, 356, 420, 484};

    for (int l = 0; l < NLAY; l++) {
        const float *hin, *ba, *ga, *bea, *bb, *gb, *bbb;
        int K1;
        if (l == 0) {
            hin = x; K1 = DINF;
            ba = b1_0; ga = g1_0; bea = be1_0;
            bb = b2_0; gb = gbn_0; bbb = bbn_0;
        } else {
            hin = hbuf; K1 = DHF;
            int o1 = (l - 1) * DHF;
            ba = b1_r + o1; ga = g1_r + o1; bea = be1_r + o1;
            bb = b2_r + o1; gb = gbn_r + o1; bbb = bbn_r + o1;
        }
        k_layer<<<lgrid, 256>>>(hin, eps, l, K1,
                                wpk + woff_g1[l] * DHF, ba,
                                wpk + woff_g2[l] * DHF, bb,
                                ga, bea, gb, bbb,
                                gid, out, DINF + l * DHF,
                                (l < NLAY - 1) ? 1 : 0,
                                (l == 0) ? 1 : 0);
    }
}